// round 4
// baseline (speedup 1.0000x reference)
#include <cuda_runtime.h>
#include <cstdint>
#include <math.h>

#define TT 128
#define BB 32
#define HH 256
#define II 256
#define G4 1024   // 4*H
#define CL 8      // CTAs per cluster
#define BPC 2     // batch elements per cluster
#define NTH 512

// Scratch for hoisted input projection: xproj[t][b][row] = emb@W_ih^T + b_ih + b_hh
__device__ float g_xproj[(size_t)TT * BB * G4];  // 16 MB

// ---------------------------------------------------------------------------
// Kernel A: xproj = emb @ W_ih^T + (b_ih + b_hh)   (M=4096, N=1024, K=256)
// ---------------------------------------------------------------------------
__global__ void __launch_bounds__(256) xproj_kernel(
    const float* __restrict__ emb, const float* __restrict__ W_ih,
    const float* __restrict__ b_ih, const float* __restrict__ b_hh)
{
    __shared__ float As[64][65];
    __shared__ float Bs[64][65];
    const int K = II;
    const int bm = blockIdx.x * 64, bn = blockIdx.y * 64;
    const int tx = threadIdx.x & 15, ty = threadIdx.x >> 4;
    float acc[4][4] = {};

    for (int k0 = 0; k0 < K; k0 += 64) {
        for (int i = threadIdx.x; i < 64 * 64; i += 256) {
            int r = i >> 6, cc = i & 63;
            As[r][cc] = emb[(size_t)(bm + r) * K + k0 + cc];
            Bs[r][cc] = W_ih[(size_t)(bn + r) * K + k0 + cc];
        }
        __syncthreads();
        #pragma unroll
        for (int k = 0; k < 64; k++) {
            float a[4], bv[4];
            #pragma unroll
            for (int i = 0; i < 4; i++) a[i] = As[ty * 4 + i][k];
            #pragma unroll
            for (int j = 0; j < 4; j++) bv[j] = Bs[tx * 4 + j][k];
            #pragma unroll
            for (int i = 0; i < 4; i++)
                #pragma unroll
                for (int j = 0; j < 4; j++)
                    acc[i][j] += a[i] * bv[j];
        }
        __syncthreads();
    }
    #pragma unroll
    for (int i = 0; i < 4; i++)
        #pragma unroll
        for (int j = 0; j < 4; j++) {
            int r = bm + ty * 4 + i, cI = bn + tx * 4 + j;
            g_xproj[(size_t)r * G4 + cI] = acc[i][j] + b_ih[cI] + b_hh[cI];
        }
}

// ---------------------------------------------------------------------------
// DSMEM / mbarrier helpers
// ---------------------------------------------------------------------------
__device__ __forceinline__ uint32_t smem_u32(const void* p) {
    return (uint32_t)__cvta_generic_to_shared(p);
}
__device__ __forceinline__ uint32_t my_rank() {
    uint32_t r;
    asm("mov.u32 %0, %%cluster_ctarank;" : "=r"(r));
    return r;
}
__device__ __forceinline__ void red_cluster_add(uint32_t laddr, int rank, float v) {
    uint32_t ra;
    asm volatile("mapa.shared::cluster.u32 %0, %1, %2;" : "=r"(ra) : "r"(laddr), "r"(rank));
    asm volatile("red.relaxed.cluster.shared::cluster.add.f32 [%0], %1;"
                 :: "r"(ra), "f"(v) : "memory");
}
__device__ __forceinline__ void bar_arrive_rank(uint32_t lbar, int rank) {
    uint32_t ra;
    asm volatile("mapa.shared::cluster.u32 %0, %1, %2;" : "=r"(ra) : "r"(lbar), "r"(rank));
    asm volatile("mbarrier.arrive.release.cluster.shared::cluster.b64 _, [%0];"
                 :: "r"(ra) : "memory");
}
__device__ __forceinline__ void bar_wait(uint32_t lbar, uint32_t parity) {
    asm volatile(
        "{\n\t.reg .pred P;\n\t"
        "LW_%=:\n\t"
        "mbarrier.try_wait.parity.acquire.cluster.shared::cta.b64 P, [%0], %1, 0x989680;\n\t"
        "@P bra LD_%=;\n\t"
        "bra LW_%=;\n\t"
        "LD_%=:\n\t}"
        :: "r"(lbar), "r"(parity) : "memory");
}

// ---------------------------------------------------------------------------
// Kernel B: 8-CTA cluster per 2 batch elements. Rank r owns the j-slice
// [32r, 32r+32): history buf[:,j32], h[j32], c[j32], W_a columns
// {j32, 256+j32} (in registers), W_hh columns j32 (in SMEM), hu rows
// [32r,32r+32). All cross-rank data flows via red.add.f32 partial-sum
// reductions. 3 cluster barriers per step.
// ---------------------------------------------------------------------------
__global__ void __launch_bounds__(NTH, 1) __cluster_dims__(CL, 1, 1)
recur_kernel(
    const int*   __restrict__ lens,
    const float* __restrict__ W_hh,   // [1024, 256]
    const float* __restrict__ W_a,    // [256, 512]
    const float* __restrict__ b_a,    // [256]
    float* __restrict__ out)          // output[T,B,H] ++ h_fin[B,H] ++ c_fin[B,H]
{
    extern __shared__ float smf[];
    unsigned long long* mbar = (unsigned long long*)smf;     // 3 barriers
    float* whh  = smf + 8;          // [16][2048] W_hh K-slice, interleaved (128 KB)
    float* buf  = whh  + 32768;     // [2][128][32] history j-slice (32 KB)
    float* gred = buf  + 8192;      // [2 par][2 gb][1024] gate red targets (16 KB)
    float* yred = gred + 4096;      // [2 par][2 gb][256] combine red targets
    float* sc   = yred + 1024;      // [2 par][2 gb][128] score red targets -> alpha
    float* catL = sc   + 512;       // [2 gb][64] local [ctx_j32, h_j32]
    float* h_s  = catL + 128;       // [2][32]
    float* c_s  = h_s  + 64;        // [2][32]
    float* hu_s = c_s  + 64;        // [2][32]
    // total floats: 8 + 32768 + 8192 + 4096 + 1024 + 512 + 128 + 192 = 46920

    const int tid  = threadIdx.x;
    const int warp = tid >> 5, lane = tid & 31;
    const int r    = (int)my_rank();
    const int b0   = (blockIdx.x / CL) * BPC;
    const int len0 = lens[b0], len1 = lens[b0 + 1];

    const uint32_t bar0 = smem_u32(&mbar[0]);
    const uint32_t bar1 = smem_u32(&mbar[1]);
    const uint32_t bar2 = smem_u32(&mbar[2]);

    // ---- one-time: load W_hh K-slice into SMEM, interleaved for float4 reads
    // whh[kk*2048 + (row>>1)*4 + (k&1)*2 + (row&1)] = W_hh[row][32r + k]
    for (int idx = tid; idx < 32768; idx += NTH) {
        int row = idx >> 5, k = idx & 31;
        float v = W_hh[(size_t)row * HH + 32 * r + k];
        whh[(k >> 1) * 2048 + (row >> 1) * 4 + (k & 1) * 2 + (row & 1)] = v;
    }
    // ---- one-time: W_a slice into registers (thread-per-row, K=64 local cols)
    float wa[64];
    {
        int row = 32 * (warp >> 1) + lane;
        #pragma unroll
        for (int k = 0; k < 64; k++) {
            int col = (k < 32) ? (32 * r + k) : (256 + 32 * r + (k - 32));
            wa[k] = W_a[(size_t)row * 512 + col];
        }
    }
    // ---- zero all red buffers + state (gred..hu_s contiguous: 5952 floats)
    for (int idx = tid; idx < 5952; idx += NTH) gred[idx] = 0.f;

    if (tid == 0) {
        #pragma unroll
        for (int k = 0; k < 3; k++)
            asm volatile("mbarrier.init.shared.b64 [%0], %1;"
                         :: "r"(smem_u32(&mbar[k])), "r"(CL) : "memory");
        asm volatile("fence.mbarrier_init.release.cluster;" ::: "memory");
    }
    __syncthreads();
    asm volatile("barrier.cluster.arrive.aligned;" ::: "memory");
    asm volatile("barrier.cluster.wait.aligned;" ::: "memory");

    for (int t = 0; t < TT; t++) {
        const uint32_t par = (uint32_t)(t & 1);

        // ======== P1: score partials over my j-slice, red to all ranks ======
        if (t > 0) {
            int gb = warp >> 3, s0 = warp & 7;
            float hv = h_s[gb * 32 + lane];
            for (int s = s0; s < t; s += 8) {
                float v = buf[(gb * TT + s) * 32 + lane] * hv;
                #pragma unroll
                for (int o = 16; o > 0; o >>= 1) v += __shfl_xor_sync(0xffffffffu, v, o);
                if (lane < CL)
                    red_cluster_add(smem_u32(&sc[(par * 2 + gb) * TT + s]), lane, v);
            }
        }
        __syncthreads();
        if (tid < CL) bar_arrive_rank(bar0, tid);
        bar_wait(bar0, par);                                          // B1

        // ======== P2: softmax (local) -> alpha; ctx j-slice; y partial ======
        if (t > 0 && warp < BPC) {
            int gb = warp;
            float* scg = &sc[(par * 2 + gb) * TT];
            float m = -1e30f;
            for (int s = lane; s < t; s += 32) m = fmaxf(m, scg[s]);
            #pragma unroll
            for (int o = 16; o > 0; o >>= 1) m = fmaxf(m, __shfl_xor_sync(0xffffffffu, m, o));
            float sum = 0.f;
            for (int s = lane; s < t; s += 32) { float e = __expf(scg[s] - m); scg[s] = e; sum += e; }
            #pragma unroll
            for (int o = 16; o > 0; o >>= 1) sum += __shfl_xor_sync(0xffffffffu, sum, o);
            float inv = 1.f / sum;
            for (int s = lane; s < t; s += 32) scg[s] *= inv;
        }
        __syncthreads();

        if (tid < 64) {
            int gb = tid >> 5, jl = tid & 31;
            const float* scg = &sc[(par * 2 + gb) * TT];
            float acc = 0.f;
            for (int s = 0; s < t; s++) acc += scg[s] * buf[(gb * TT + s) * 32 + jl];
            catL[gb * 64 + jl]      = acc;
            catL[gb * 64 + 32 + jl] = h_s[gb * 32 + jl];
        } else if (tid >= 256) {
            // zero next-parity score buffer (receives reds at t+1)
            sc[((par ^ 1u) * 2) * TT + (tid - 256)] = 0.f;   // 256 floats = both gb
        }
        __syncthreads();

        if (t > 0) {
            int gb = warp & 1, row = 32 * (warp >> 1) + lane;
            const float* cg = &catL[gb * 64];
            float acc = 0.f;
            #pragma unroll
            for (int k = 0; k < 64; k += 4) {
                float4 x = *(const float4*)&cg[k];
                acc += wa[k] * x.x + wa[k + 1] * x.y + wa[k + 2] * x.z + wa[k + 3] * x.w;
            }
            red_cluster_add(smem_u32(&yred[(par * 2 + gb) * 256 + row]), row >> 5, acc);
        }
        __syncthreads();
        if (tid < CL) bar_arrive_rank(bar1, tid);
        bar_wait(bar1, par);                                          // B2

        // ======== P3: hu my rows; gates K-slice partial GEMV; red to owners =
        float xp0 = 0.f, xp1 = 0.f, xp2 = 0.f, xp3 = 0.f;
        if (tid < 64) {
            int gb = tid >> 5, jl = tid & 31, j = 32 * r + jl;
            const float* xp = g_xproj + ((size_t)t * BB + b0 + gb) * G4;
            xp0 = __ldg(&xp[j]);        xp1 = __ldg(&xp[256 + j]);
            xp2 = __ldg(&xp[512 + j]);  xp3 = __ldg(&xp[768 + j]);
            float v = yred[(par * 2 + gb) * 256 + j];
            yred[(par * 2 + gb) * 256 + j] = 0.f;
            hu_s[gb * 32 + jl] = (t > 0) ? tanhf(v + __ldg(&b_a[j])) : 0.f;
        }
        __syncthreads();
        {
            float a00 = 0.f, a10 = 0.f, a01 = 0.f, a11 = 0.f;
            #pragma unroll
            for (int kk = 0; kk < 16; kk++) {
                float4 w4 = *(const float4*)&whh[kk * 2048 + tid * 4];
                float2 h0 = *(const float2*)&hu_s[2 * kk];
                float2 h1 = *(const float2*)&hu_s[32 + 2 * kk];
                a00 += w4.x * h0.x + w4.z * h0.y;
                a10 += w4.y * h0.x + w4.w * h0.y;
                a01 += w4.x * h1.x + w4.z * h1.y;
                a11 += w4.y * h1.x + w4.w * h1.y;
            }
            int row0 = 2 * tid, row1 = row0 + 1;
            int owner = (row0 & 255) >> 5;        // row0 even -> same owner for row1
            red_cluster_add(smem_u32(&gred[(par * 2 + 0) * 1024 + row0]), owner, a00);
            red_cluster_add(smem_u32(&gred[(par * 2 + 0) * 1024 + row1]), owner, a10);
            red_cluster_add(smem_u32(&gred[(par * 2 + 1) * 1024 + row0]), owner, a01);
            red_cluster_add(smem_u32(&gred[(par * 2 + 1) * 1024 + row1]), owner, a11);
        }
        __syncthreads();
        if (tid < CL) bar_arrive_rank(bar2, tid);
        bar_wait(bar2, par);                                          // B3

        // ======== P4: LSTM cell on my j-slice (all local) ====================
        if (tid < 64) {
            int gb = tid >> 5, jl = tid & 31, j = 32 * r + jl;
            float* gb_gred = &gred[(par * 2 + gb) * 1024];
            float ig = gb_gred[j]       + xp0;  gb_gred[j]       = 0.f;
            float fg = gb_gred[256 + j] + xp1;  gb_gred[256 + j] = 0.f;
            float gg = gb_gred[512 + j] + xp2;  gb_gred[512 + j] = 0.f;
            float og = gb_gred[768 + j] + xp3;  gb_gred[768 + j] = 0.f;
            float si = 1.f / (1.f + __expf(-ig));
            float sf = 1.f / (1.f + __expf(-fg));
            float so = 1.f / (1.f + __expf(-og));
            float cn = sf * c_s[gb * 32 + jl] + si * tanhf(gg);
            float hn = so * tanhf(cn);
            c_s[gb * 32 + jl] = cn;
            h_s[gb * 32 + jl] = hn;
            buf[(gb * TT + t) * 32 + jl] = hn;

            int b = b0 + gb;
            out[((size_t)t * BB + b) * HH + j] = hn;
            int ln = gb ? len1 : len0;
            if (t == ln - 1) {
                out[(size_t)TT * BB * HH + (size_t)b * HH + j] = hn;
                out[(size_t)TT * BB * HH + (size_t)BB * HH + (size_t)b * HH + j] = cn;
            }
        }
        __syncthreads();
    }
}

// ---------------------------------------------------------------------------
extern "C" void kernel_launch(void* const* d_in, const int* in_sizes, int n_in,
                              void* d_out, int out_size)
{
    const float* embs = (const float*)d_in[0];
    const int*   lens = (const int*)  d_in[1];
    const float* W_ih = (const float*)d_in[2];
    const float* W_hh = (const float*)d_in[3];
    const float* b_ih = (const float*)d_in[4];
    const float* b_hh = (const float*)d_in[5];
    const float* W_a  = (const float*)d_in[6];
    const float* b_a  = (const float*)d_in[7];
    float* out = (float*)d_out;

    const int smem_bytes = 46920 * (int)sizeof(float);   // ~183 KB
    cudaFuncSetAttribute(recur_kernel, cudaFuncAttributeMaxDynamicSharedMemorySize, smem_bytes);

    xproj_kernel<<<dim3((TT * BB) / 64, G4 / 64), 256>>>(embs, W_ih, b_ih, b_hh);
    recur_kernel<<<(BB / BPC) * CL, NTH, smem_bytes>>>(lens, W_hh, W_a, b_a, out);
}

// round 5
// speedup vs baseline: 1.4129x; 1.4129x over previous
#include <cuda_runtime.h>
#include <cstdint>
#include <math.h>

#define TT 128
#define BB 32
#define HH 256
#define II 256
#define G4 1024   // 4*H
#define CL 8      // CTAs per cluster
#define BPC 2     // batch elements per cluster
#define NTH 512

// Scratch for hoisted input projection: xproj[t][b][row] = emb@W_ih^T + b_ih + b_hh
__device__ float g_xproj[(size_t)TT * BB * G4];  // 16 MB

// ---------------------------------------------------------------------------
// Kernel A: xproj = emb @ W_ih^T + (b_ih + b_hh)   (M=4096, N=1024, K=256)
// ---------------------------------------------------------------------------
__global__ void __launch_bounds__(256) xproj_kernel(
    const float* __restrict__ emb, const float* __restrict__ W_ih,
    const float* __restrict__ b_ih, const float* __restrict__ b_hh)
{
    __shared__ float As[64][65];
    __shared__ float Bs[64][65];
    const int K = II;
    const int bm = blockIdx.x * 64, bn = blockIdx.y * 64;
    const int tx = threadIdx.x & 15, ty = threadIdx.x >> 4;
    float acc[4][4] = {};

    for (int k0 = 0; k0 < K; k0 += 64) {
        for (int i = threadIdx.x; i < 64 * 64; i += 256) {
            int r = i >> 6, cc = i & 63;
            As[r][cc] = emb[(size_t)(bm + r) * K + k0 + cc];
            Bs[r][cc] = W_ih[(size_t)(bn + r) * K + k0 + cc];
        }
        __syncthreads();
        #pragma unroll
        for (int k = 0; k < 64; k++) {
            float a[4], bv[4];
            #pragma unroll
            for (int i = 0; i < 4; i++) a[i] = As[ty * 4 + i][k];
            #pragma unroll
            for (int j = 0; j < 4; j++) bv[j] = Bs[tx * 4 + j][k];
            #pragma unroll
            for (int i = 0; i < 4; i++)
                #pragma unroll
                for (int j = 0; j < 4; j++)
                    acc[i][j] += a[i] * bv[j];
        }
        __syncthreads();
    }
    #pragma unroll
    for (int i = 0; i < 4; i++)
        #pragma unroll
        for (int j = 0; j < 4; j++) {
            int r = bm + ty * 4 + i, cI = bn + tx * 4 + j;
            g_xproj[(size_t)r * G4 + cI] = acc[i][j] + b_ih[cI] + b_hh[cI];
        }
}

// ---------------------------------------------------------------------------
// DSMEM / mbarrier helpers (plain stores only — NO cluster atomics)
// ---------------------------------------------------------------------------
__device__ __forceinline__ uint32_t smem_u32(const void* p) {
    return (uint32_t)__cvta_generic_to_shared(p);
}
__device__ __forceinline__ uint32_t my_rank() {
    uint32_t r;
    asm("mov.u32 %0, %%cluster_ctarank;" : "=r"(r));
    return r;
}
__device__ __forceinline__ void st_cluster(uint32_t laddr, int rank, float v) {
    uint32_t ra;
    asm volatile("mapa.shared::cluster.u32 %0, %1, %2;" : "=r"(ra) : "r"(laddr), "r"(rank));
    asm volatile("st.shared::cluster.f32 [%0], %1;" :: "r"(ra), "f"(v) : "memory");
}
__device__ __forceinline__ void bar_arrive_rank(uint32_t lbar, int rank) {
    uint32_t ra;
    asm volatile("mapa.shared::cluster.u32 %0, %1, %2;" : "=r"(ra) : "r"(lbar), "r"(rank));
    asm volatile("mbarrier.arrive.release.cluster.shared::cluster.b64 _, [%0];"
                 :: "r"(ra) : "memory");
}
__device__ __forceinline__ void bar_wait(uint32_t lbar, uint32_t parity) {
    asm volatile(
        "{\n\t.reg .pred P;\n\t"
        "LW_%=:\n\t"
        "mbarrier.try_wait.parity.acquire.cluster.shared::cta.b64 P, [%0], %1, 0x989680;\n\t"
        "@P bra LD_%=;\n\t"
        "bra LW_%=;\n\t"
        "LD_%=:\n\t}"
        :: "r"(lbar), "r"(parity) : "memory");
}

// ---------------------------------------------------------------------------
// Kernel B: 8-CTA cluster per 2 batch elements (16 clusters = 128 CTAs).
// Rank r owns: j-slice [32r,32r+32) of h/c/history, W_hh rows
// {g*256 + 32r + jl} (SMEM-resident, loaded once), W_a rows [32r,32r+32)
// (registers). Cross-rank data flows only via plain st.cluster all-gathers.
// 3 cluster barriers per step.
// ---------------------------------------------------------------------------
__global__ void __launch_bounds__(NTH, 1) __cluster_dims__(CL, 1, 1)
recur_kernel(
    const int*   __restrict__ lens,
    const float* __restrict__ W_hh,   // [1024, 256]
    const float* __restrict__ W_a,    // [256, 512]
    const float* __restrict__ b_a,    // [256]
    float* __restrict__ out)          // output[T,B,H] ++ h_fin[B,H] ++ c_fin[B,H]
{
    extern __shared__ float smf[];
    unsigned long long* mbar = (unsigned long long*)smf;   // 3 barriers (first 8 floats)
    float* whh    = smf + 8;            // [128 rows][4 q][68] = 34816 (136 KB, padded)
    float* buf    = whh    + 34816;     // [2][128][32] history j-slice (32 KB)
    float* scpart = buf    + 8192;      // [2 gb][8 src][128] score partials (8 KB)
    float* alpha  = scpart + 2048;      // [2][128]
    float* cat    = alpha  + 256;       // [2][512]  gathered [ctx, h] (full)
    float* huG    = cat    + 1024;      // [2][256]  gathered hu (full)
    float* gates  = huG    + 512;       // [2][128]  my gate rows
    float* xps    = gates  + 256;       // [2][128]  staged xproj slice
    float* h_s    = xps    + 256;       // [2][32]
    float* c_s    = h_s    + 64;        // [2][32]
    // total: 8 + 34816 + 8192 + 2048 + 256 + 1024 + 512 + 256 + 256 + 64 + 64
    //      = 47496 floats = 189,984 B

    const int tid  = threadIdx.x;
    const int warp = tid >> 5, lane = tid & 31;
    const int r    = (int)my_rank();
    const int b0   = (blockIdx.x / CL) * BPC;
    const int len0 = lens[b0], len1 = lens[b0 + 1];

    const uint32_t bar0 = smem_u32(&mbar[0]);
    const uint32_t bar1 = smem_u32(&mbar[1]);
    const uint32_t bar2 = smem_u32(&mbar[2]);

    // ---- one-time: W_hh row-slice into SMEM (128 rows x 256 cols, padded) --
    // local row lr = g*32 + jl  ->  global row (lr>>5)*256 + 32r + (lr&31)
    for (int lr = warp; lr < 128; lr += 16) {
        int grow = (lr >> 5) * 256 + 32 * r + (lr & 31);
        #pragma unroll
        for (int half = 0; half < 2; half++) {
            int k = half * 128 + lane * 4;
            float4 w = *(const float4*)&W_hh[(size_t)grow * HH + k];
            int q = k >> 6, rem = k & 63;
            *(float4*)&whh[lr * 272 + q * 68 + rem] = w;
        }
    }
    // ---- one-time: W_a slice into registers: thread (row=tid>>4, kt=tid&15)
    float wa[32];
    float ba_r;
    {
        int row = tid >> 4, kt = tid & 15;
        const float* wr = &W_a[(size_t)(32 * r + row) * 512 + kt * 32];
        #pragma unroll
        for (int i = 0; i < 32; i += 4) {
            float4 w = *(const float4*)&wr[i];
            wa[i] = w.x; wa[i + 1] = w.y; wa[i + 2] = w.z; wa[i + 3] = w.w;
        }
        ba_r = __ldg(&b_a[32 * r + row]);
    }
    // ---- zero state ----
    if (tid < 512) huG[tid] = 0.f;
    if (tid < 128) { h_s[tid & 63] = 0.f; c_s[tid & 63] = 0.f; }   // 64+64
    if (tid == 0) {
        #pragma unroll
        for (int k = 0; k < 3; k++)
            asm volatile("mbarrier.init.shared.b64 [%0], %1;"
                         :: "r"(smem_u32(&mbar[k])), "r"(CL) : "memory");
        asm volatile("fence.mbarrier_init.release.cluster;" ::: "memory");
    }
    __syncthreads();
    asm volatile("barrier.cluster.arrive.aligned;" ::: "memory");
    asm volatile("barrier.cluster.wait.aligned;" ::: "memory");

    for (int t = 0; t < TT; t++) {
        const uint32_t par = (uint32_t)(t & 1);

        // ---- stage xproj slice (hidden behind P1 + B1) ----
        if (tid < 256) {
            int gb = tid >> 7, lr = tid & 127;
            int grow = (lr >> 5) * 256 + 32 * r + (lr & 31);
            xps[gb * 128 + lr] = __ldg(&g_xproj[((size_t)t * BB + b0 + gb) * G4 + grow]);
        }

        // ======== P1: score partials over my j-slice, broadcast to peers ====
        if (t > 0) {
            int gb = warp >> 3;
            float hv = h_s[gb * 32 + lane];
            for (int s = (warp & 7); s < t; s += 8) {
                float v = buf[(gb * TT + s) * 32 + lane] * hv;
                #pragma unroll
                for (int o = 16; o > 0; o >>= 1) v += __shfl_xor_sync(0xffffffffu, v, o);
                if (lane < CL)
                    st_cluster(smem_u32(&scpart[(gb * CL + r) * TT + s]), lane, v);
            }
        }
        __syncthreads();
        if (tid < CL) bar_arrive_rank(bar0, tid);
        bar_wait(bar0, par);                                          // B1

        // ======== P2: sum partials + softmax (local); ctx j-slice; gather cat
        if (t > 0) {
            if (warp < BPC) {
                int gb = warp;
                float v[4];
                float m = -1e30f;
                #pragma unroll
                for (int c = 0; c < 4; c++) {
                    int s = lane + 32 * c;
                    float sum = -1e30f;
                    if (s < t) {
                        sum = 0.f;
                        #pragma unroll
                        for (int src = 0; src < CL; src++)
                            sum += scpart[(gb * CL + src) * TT + s];
                    }
                    v[c] = sum;
                    m = fmaxf(m, sum);
                }
                #pragma unroll
                for (int o = 16; o > 0; o >>= 1) m = fmaxf(m, __shfl_xor_sync(0xffffffffu, m, o));
                float tot = 0.f;
                #pragma unroll
                for (int c = 0; c < 4; c++) {
                    int s = lane + 32 * c;
                    if (s < t) { v[c] = __expf(v[c] - m); tot += v[c]; }
                }
                #pragma unroll
                for (int o = 16; o > 0; o >>= 1) tot += __shfl_xor_sync(0xffffffffu, tot, o);
                float inv = 1.f / tot;
                #pragma unroll
                for (int c = 0; c < 4; c++) {
                    int s = lane + 32 * c;
                    if (s < t) alpha[gb * TT + s] = v[c] * inv;
                }
            }
            __syncthreads();

            if (tid < 64) {
                int gb = tid >> 5, jl = tid & 31;
                float acc = 0.f;
                const float* al = &alpha[gb * TT];
                const float* bb = &buf[gb * TT * 32 + jl];
                int s = 0;
                for (; s + 4 <= t; s += 4) {
                    acc += al[s] * bb[s * 32] + al[s + 1] * bb[(s + 1) * 32]
                         + al[s + 2] * bb[(s + 2) * 32] + al[s + 3] * bb[(s + 3) * 32];
                }
                for (; s < t; s++) acc += al[s] * bb[s * 32];

                float hv = h_s[gb * 32 + jl];
                uint32_t ac = smem_u32(&cat[gb * 512 + 32 * r + jl]);
                uint32_t ah = smem_u32(&cat[gb * 512 + 256 + 32 * r + jl]);
                #pragma unroll
                for (int peer = 0; peer < CL; peer++) {
                    st_cluster(ac, peer, acc);
                    st_cluster(ah, peer, hv);
                }
            }
        }
        __syncthreads();
        if (tid < CL) bar_arrive_rank(bar1, tid);
        bar_wait(bar1, par);                                          // B2

        // ======== P3: combine GEMV for my 32 hu rows, gather hu =============
        if (t > 0) {
            int kt = tid & 15;          // k-thread within row
            float a0 = 0.f, a1 = 0.f;
            #pragma unroll
            for (int k4 = 0; k4 < 8; k4++) {
                float4 x0 = *(const float4*)&cat[0 * 512 + kt * 32 + k4 * 4];
                float4 x1 = *(const float4*)&cat[1 * 512 + kt * 32 + k4 * 4];
                a0 += wa[k4 * 4] * x0.x + wa[k4 * 4 + 1] * x0.y
                    + wa[k4 * 4 + 2] * x0.z + wa[k4 * 4 + 3] * x0.w;
                a1 += wa[k4 * 4] * x1.x + wa[k4 * 4 + 1] * x1.y
                    + wa[k4 * 4 + 2] * x1.z + wa[k4 * 4 + 3] * x1.w;
            }
            #pragma unroll
            for (int o = 8; o > 0; o >>= 1) {
                a0 += __shfl_xor_sync(0xffffffffu, a0, o);
                a1 += __shfl_xor_sync(0xffffffffu, a1, o);
            }
            // all 16 lanes of the group hold the sums
            int row = tid >> 4;
            int gbW = kt >> 3, peer = kt & 7;
            float hv = tanhf(((gbW == 0) ? a0 : a1) + ba_r);
            st_cluster(smem_u32(&huG[gbW * 256 + 32 * r + row]), peer, hv);
        }
        __syncthreads();
        if (tid < CL) bar_arrive_rank(bar2, tid);
        bar_wait(bar2, par);                                          // B3

        // ======== P4: gates GEMV from SMEM-resident W_hh (local) ============
        {
            int lr = tid >> 2, q = tid & 3;
            const float* wrow = &whh[lr * 272 + q * 68];
            const float* x0p  = &huG[0 * 256 + q * 64];
            const float* x1p  = &huG[1 * 256 + q * 64];
            float a0 = 0.f, a1 = 0.f;
            #pragma unroll
            for (int k4 = 0; k4 < 16; k4++) {
                float4 w  = *(const float4*)&wrow[k4 * 4];
                float4 x0 = *(const float4*)&x0p[k4 * 4];
                float4 x1 = *(const float4*)&x1p[k4 * 4];
                a0 += w.x * x0.x + w.y * x0.y + w.z * x0.z + w.w * x0.w;
                a1 += w.x * x1.x + w.y * x1.y + w.z * x1.z + w.w * x1.w;
            }
            a0 += __shfl_xor_sync(0xffffffffu, a0, 1);
            a0 += __shfl_xor_sync(0xffffffffu, a0, 2);
            a1 += __shfl_xor_sync(0xffffffffu, a1, 1);
            a1 += __shfl_xor_sync(0xffffffffu, a1, 2);
            if (q == 0) {
                gates[0 * 128 + lr] = a0 + xps[0 * 128 + lr];
                gates[1 * 128 + lr] = a1 + xps[1 * 128 + lr];
            }
        }
        __syncthreads();

        // ======== cell update on my j-slice (all local) =====================
        if (tid < 64) {
            int gb = tid >> 5, jl = tid & 31, j = 32 * r + jl;
            float ig = gates[gb * 128 + jl];
            float fg = gates[gb * 128 + 32 + jl];
            float gg = gates[gb * 128 + 64 + jl];
            float og = gates[gb * 128 + 96 + jl];
            float si = 1.f / (1.f + __expf(-ig));
            float sf = 1.f / (1.f + __expf(-fg));
            float so = 1.f / (1.f + __expf(-og));
            float cn = sf * c_s[gb * 32 + jl] + si * tanhf(gg);
            float hn = so * tanhf(cn);
            c_s[gb * 32 + jl] = cn;
            h_s[gb * 32 + jl] = hn;
            buf[(gb * TT + t) * 32 + jl] = hn;

            int b = b0 + gb;
            out[((size_t)t * BB + b) * HH + j] = hn;
            int ln = gb ? len1 : len0;
            if (t == ln - 1) {
                out[(size_t)TT * BB * HH + (size_t)b * HH + j] = hn;
                out[(size_t)TT * BB * HH + (size_t)BB * HH + (size_t)b * HH + j] = cn;
            }
        }
        __syncthreads();
    }
}

// ---------------------------------------------------------------------------
extern "C" void kernel_launch(void* const* d_in, const int* in_sizes, int n_in,
                              void* d_out, int out_size)
{
    const float* embs = (const float*)d_in[0];
    const int*   lens = (const int*)  d_in[1];
    const float* W_ih = (const float*)d_in[2];
    const float* W_hh = (const float*)d_in[3];
    const float* b_ih = (const float*)d_in[4];
    const float* b_hh = (const float*)d_in[5];
    const float* W_a  = (const float*)d_in[6];
    const float* b_a  = (const float*)d_in[7];
    float* out = (float*)d_out;

    const int smem_bytes = 47496 * (int)sizeof(float);   // ~185.5 KB
    cudaFuncSetAttribute(recur_kernel, cudaFuncAttributeMaxDynamicSharedMemorySize, smem_bytes);

    xproj_kernel<<<dim3((TT * BB) / 64, G4 / 64), 256>>>(embs, W_ih, b_ih, b_hh);
    recur_kernel<<<(BB / BPC) * CL, NTH, smem_bytes>>>(lens, W_hh, W_a, b_a, out);
}

// round 6
// speedup vs baseline: 4.4587x; 3.1558x over previous
#include <cuda_runtime.h>
#include <cstdint>
#include <math.h>

#define TT 128
#define BB 32
#define HH 256
#define II 256
#define G4 1024   // 4*H
#define CL 4      // CTAs per cluster (proven sweet spot)
#define NTH 512
#define JS 64     // j-slice per rank (HH/CL)

// Scratch for hoisted input projection: xproj[t][b][row] = emb@W_ih^T + b_ih + b_hh
__device__ float g_xproj[(size_t)TT * BB * G4];  // 16 MB

// ---------------------------------------------------------------------------
// Kernel A: xproj = emb @ W_ih^T + (b_ih + b_hh)   (M=4096, N=1024, K=256)
// ---------------------------------------------------------------------------
__global__ void __launch_bounds__(256) xproj_kernel(
    const float* __restrict__ emb, const float* __restrict__ W_ih,
    const float* __restrict__ b_ih, const float* __restrict__ b_hh)
{
    __shared__ float As[64][65];
    __shared__ float Bs[64][65];
    const int K = II;
    const int bm = blockIdx.x * 64, bn = blockIdx.y * 64;
    const int tx = threadIdx.x & 15, ty = threadIdx.x >> 4;
    float acc[4][4] = {};

    for (int k0 = 0; k0 < K; k0 += 64) {
        for (int i = threadIdx.x; i < 64 * 64; i += 256) {
            int r = i >> 6, cc = i & 63;
            As[r][cc] = emb[(size_t)(bm + r) * K + k0 + cc];
            Bs[r][cc] = W_ih[(size_t)(bn + r) * K + k0 + cc];
        }
        __syncthreads();
        #pragma unroll
        for (int k = 0; k < 64; k++) {
            float a[4], bv[4];
            #pragma unroll
            for (int i = 0; i < 4; i++) a[i] = As[ty * 4 + i][k];
            #pragma unroll
            for (int j = 0; j < 4; j++) bv[j] = Bs[tx * 4 + j][k];
            #pragma unroll
            for (int i = 0; i < 4; i++)
                #pragma unroll
                for (int j = 0; j < 4; j++)
                    acc[i][j] += a[i] * bv[j];
        }
        __syncthreads();
    }
    #pragma unroll
    for (int i = 0; i < 4; i++)
        #pragma unroll
        for (int j = 0; j < 4; j++) {
            int r = bm + ty * 4 + i, cI = bn + tx * 4 + j;
            g_xproj[(size_t)r * G4 + cI] = acc[i][j] + b_ih[cI] + b_hh[cI];
        }
}

// ---------------------------------------------------------------------------
// DSMEM / mbarrier helpers (plain stores, no atomics)
// ---------------------------------------------------------------------------
__device__ __forceinline__ uint32_t smem_u32(const void* p) {
    return (uint32_t)__cvta_generic_to_shared(p);
}
__device__ __forceinline__ uint32_t my_rank() {
    uint32_t r;
    asm("mov.u32 %0, %%cluster_ctarank;" : "=r"(r));
    return r;
}
__device__ __forceinline__ void st_cluster(uint32_t laddr, int rank, float v) {
    uint32_t ra;
    asm volatile("mapa.shared::cluster.u32 %0, %1, %2;" : "=r"(ra) : "r"(laddr), "r"(rank));
    asm volatile("st.shared::cluster.f32 [%0], %1;" :: "r"(ra), "f"(v) : "memory");
}
__device__ __forceinline__ void bar_arrive_rank(uint32_t lbar, int rank) {
    uint32_t ra;
    asm volatile("mapa.shared::cluster.u32 %0, %1, %2;" : "=r"(ra) : "r"(lbar), "r"(rank));
    asm volatile("mbarrier.arrive.release.cluster.shared::cluster.b64 _, [%0];"
                 :: "r"(ra) : "memory");
}
__device__ __forceinline__ void bar_wait(uint32_t lbar, uint32_t parity) {
    asm volatile(
        "{\n\t.reg .pred P;\n\t"
        "LW_%=:\n\t"
        "mbarrier.try_wait.parity.acquire.cluster.shared::cta.b64 P, [%0], %1, 0x989680;\n\t"
        "@P bra LD_%=;\n\t"
        "bra LW_%=;\n\t"
        "LD_%=:\n\t}"
        :: "r"(lbar), "r"(parity) : "memory");
}

// ---------------------------------------------------------------------------
// Kernel B: 4-CTA cluster per batch element (32 clusters = 128 CTAs).
// Rank r owns: j-slice [64r,64r+64) of h/c/history, W_a rows [64r,64r+64)
// (SMEM-resident), W_hh rows {g*256 + 64r + i} (streamed from L2),
// and z-history zbuf[s] = W_a[:, :H](rows) @ h_s (incremental attention trick:
// W_a_c @ ctx = sum_s alpha_s * zbuf[s], so ctx is never materialized).
// 3 cluster barriers per step.
// ---------------------------------------------------------------------------
__global__ void __launch_bounds__(NTH, 1) __cluster_dims__(CL, 1, 1)
recur_kernel(
    const int*   __restrict__ lens,
    const float* __restrict__ W_hh,   // [1024, 256]
    const float* __restrict__ W_a,    // [256, 512]
    const float* __restrict__ b_a,    // [256]
    float* __restrict__ out)          // output[T,B,H] ++ h_fin[B,H] ++ c_fin[B,H]
{
    extern __shared__ float smf[];
    unsigned long long* mbar = (unsigned long long*)smf;   // 3 barriers (8 floats)
    float* wac    = smf + 8;            // [64][256] W_a ctx-cols slice (64 KB)
    float* wah    = wac    + 16384;     // [64][256] W_a h-cols slice   (64 KB)
    float* zbuf   = wah    + 16384;     // [128][64] z history          (32 KB)
    float* buf    = zbuf   + 8192;      // [128][64] h history j-slice  (32 KB)
    float* scp    = buf    + 8192;      // [4 src][128] score partials
    float* alpha  = scp    + 512;       // [128]
    float* h_full = alpha  + 128;       // [256] gathered h
    float* hu_full= h_full + 256;       // [256] gathered combined hidden
    float* y1part = hu_full+ 256;       // [8][64] z-weighted-sum partials
    float* gates  = y1part + 512;       // [256] my gate rows (g*64+i)
    float* xps    = gates  + 256;       // [256] staged xproj slice
    float* c_js   = xps    + 256;       // [64] my c slice
    float* ba_s   = c_js   + 64;        // [64] my b_a rows
    // total floats: 8+16384+16384+8192+8192+512+128+256+256+512+256+256+64+64
    //             = 51464  (205,856 B)

    const int tid  = threadIdx.x;
    const int warp = tid >> 5, lane = tid & 31;
    const int r    = (int)my_rank();
    const int b    = blockIdx.x / CL;
    const int myLen = lens[b];

    const uint32_t bar0 = smem_u32(&mbar[0]);
    const uint32_t bar1 = smem_u32(&mbar[1]);
    const uint32_t bar2 = smem_u32(&mbar[2]);

    // ---- one-time: W_a slice rows [64r, 64r+64) into SMEM ----
    for (int idx = tid; idx < JS * 256; idx += NTH) {
        int row = idx >> 8, k = idx & 255;
        wac[row * 256 + k] = W_a[(size_t)(JS * r + row) * 512 + k];
        wah[row * 256 + k] = W_a[(size_t)(JS * r + row) * 512 + 256 + k];
    }
    if (tid < JS) ba_s[tid] = __ldg(&b_a[JS * r + tid]);
    if (tid < 256) { h_full[tid] = 0.f; hu_full[tid] = 0.f; }
    if (tid < JS)  c_js[tid] = 0.f;
    if (tid == 0) {
        #pragma unroll
        for (int k = 0; k < 3; k++)
            asm volatile("mbarrier.init.shared.b64 [%0], %1;"
                         :: "r"(smem_u32(&mbar[k])), "r"(CL) : "memory");
        asm volatile("fence.mbarrier_init.release.cluster;" ::: "memory");
    }
    __syncthreads();
    asm volatile("barrier.cluster.arrive.aligned;" ::: "memory");
    asm volatile("barrier.cluster.wait.aligned;" ::: "memory");

    for (int t = 0; t < TT; t++) {
        const uint32_t par = (uint32_t)(t & 1);

        // ---- stage xproj slice for my gate rows (hidden under P1) ----
        if (tid < 256) {
            int grow = (tid >> 6) * 256 + JS * r + (tid & 63);
            xps[tid] = __ldg(&g_xproj[((size_t)t * BB + b) * G4 + grow]);
        }

        // ======== P1: append z_{t-1} = W_a_c(my rows) @ h_{t-1};  ==========
        // ======== score partials over my j-slice -> broadcast     ==========
        if (t > 0) {
            // z GEMV: 16 warps x 4 rows
            #pragma unroll
            for (int rr = 0; rr < 4; rr++) {
                int row = warp * 4 + rr;
                const float* wr = &wac[row * 256];
                float acc = 0.f;
                #pragma unroll
                for (int it = 0; it < 2; it++) {
                    float4 w = *(const float4*)&wr[it * 128 + lane * 4];
                    float4 x = *(const float4*)&h_full[it * 128 + lane * 4];
                    acc += w.x * x.x + w.y * x.y + w.z * x.z + w.w * x.w;
                }
                #pragma unroll
                for (int o = 16; o > 0; o >>= 1) acc += __shfl_xor_sync(0xffffffffu, acc, o);
                if (lane == 0) zbuf[(t - 1) * JS + row] = acc;
            }
            // score partials: warp handles s = warp, warp+16, ...
            for (int s = warp; s < t; s += 16) {
                float p = 0.f;
                #pragma unroll
                for (int u = 0; u < 2; u++)
                    p += buf[s * JS + lane + 32 * u] * h_full[JS * r + lane + 32 * u];
                #pragma unroll
                for (int o = 16; o > 0; o >>= 1) p += __shfl_xor_sync(0xffffffffu, p, o);
                if (lane < CL) st_cluster(smem_u32(&scp[r * TT + s]), lane, p);
            }
        }
        __syncthreads();
        if (tid < CL) bar_arrive_rank(bar0, tid);
        bar_wait(bar0, par);                                          // B0

        // ======== P2: softmax (replicated); y = Σα·z + W_a_h@h; gather hu ==
        if (t > 0) {
            if (warp == 0) {
                float v[4];
                float m = -1e30f;
                #pragma unroll
                for (int c = 0; c < 4; c++) {
                    int s = lane + 32 * c;
                    float sum = -1e30f;
                    if (s < t)
                        sum = scp[0 * TT + s] + scp[1 * TT + s]
                            + scp[2 * TT + s] + scp[3 * TT + s];
                    v[c] = sum;
                    m = fmaxf(m, sum);
                }
                #pragma unroll
                for (int o = 16; o > 0; o >>= 1) m = fmaxf(m, __shfl_xor_sync(0xffffffffu, m, o));
                float tot = 0.f;
                #pragma unroll
                for (int c = 0; c < 4; c++) {
                    int s = lane + 32 * c;
                    if (s < t) { v[c] = __expf(v[c] - m); tot += v[c]; }
                }
                #pragma unroll
                for (int o = 16; o > 0; o >>= 1) tot += __shfl_xor_sync(0xffffffffu, tot, o);
                float inv = 1.f / tot;
                #pragma unroll
                for (int c = 0; c < 4; c++) {
                    int s = lane + 32 * c;
                    if (s < t) alpha[s] = v[c] * inv;
                }
            }
            __syncthreads();

            // y1 partials: 8 s-groups x 64 rows
            {
                int g = tid >> 6, row = tid & 63;
                float acc = 0.f;
                for (int s = g; s < t; s += 8) acc += alpha[s] * zbuf[s * JS + row];
                y1part[g * JS + row] = acc;
            }
            __syncthreads();

            // combine: 16 warps x 4 rows:  hu_row = tanh(y1 + W_a_h@h + b_a)
            #pragma unroll
            for (int rr = 0; rr < 4; rr++) {
                int row = warp * 4 + rr;
                const float* wr = &wah[row * 256];
                float acc = 0.f;
                #pragma unroll
                for (int it = 0; it < 2; it++) {
                    float4 w = *(const float4*)&wr[it * 128 + lane * 4];
                    float4 x = *(const float4*)&h_full[it * 128 + lane * 4];
                    acc += w.x * x.x + w.y * x.y + w.z * x.z + w.w * x.w;
                }
                #pragma unroll
                for (int o = 16; o > 0; o >>= 1) acc += __shfl_xor_sync(0xffffffffu, acc, o);
                if (lane < CL) {
                    float y1 = y1part[0 * JS + row] + y1part[1 * JS + row]
                             + y1part[2 * JS + row] + y1part[3 * JS + row]
                             + y1part[4 * JS + row] + y1part[5 * JS + row]
                             + y1part[6 * JS + row] + y1part[7 * JS + row];
                    float hv = tanhf(acc + y1 + ba_s[row]);
                    st_cluster(smem_u32(&hu_full[JS * r + row]), lane, hv);
                }
            }
        }
        __syncthreads();
        if (tid < CL) bar_arrive_rank(bar1, tid);
        bar_wait(bar1, par);                                          // B1

        // ======== P3: gates GEMV, W_hh streamed (my 256 rows) ===============
        #pragma unroll
        for (int grp = 0; grp < 2; grp++) {
            int lrb = warp * 16 + grp * 8;
            float acc[8] = {0.f, 0.f, 0.f, 0.f, 0.f, 0.f, 0.f, 0.f};
            #pragma unroll
            for (int it = 0; it < 2; it++) {
                float4 x = *(const float4*)&hu_full[it * 128 + lane * 4];
                #pragma unroll
                for (int rr = 0; rr < 8; rr++) {
                    int lr = lrb + rr;
                    int grow = (lr >> 6) * 256 + JS * r + (lr & 63);
                    float4 w = __ldcg((const float4*)&W_hh[(size_t)grow * HH + it * 128 + lane * 4]);
                    acc[rr] += w.x * x.x + w.y * x.y + w.z * x.z + w.w * x.w;
                }
            }
            #pragma unroll
            for (int rr = 0; rr < 8; rr++) {
                float v = acc[rr];
                #pragma unroll
                for (int o = 16; o > 0; o >>= 1) v += __shfl_xor_sync(0xffffffffu, v, o);
                if (lane == rr) gates[lrb + rr] = v + xps[lrb + rr];
            }
        }
        __syncthreads();

        // ======== cell update on my j-slice; broadcast h ====================
        if (tid < JS) {
            int j = JS * r + tid;
            float ig = gates[tid],       fg = gates[64 + tid];
            float gg = gates[128 + tid], og = gates[192 + tid];
            float si = 1.f / (1.f + __expf(-ig));
            float sf = 1.f / (1.f + __expf(-fg));
            float so = 1.f / (1.f + __expf(-og));
            float cn = sf * c_js[tid] + si * tanhf(gg);
            float hn = so * tanhf(cn);
            c_js[tid] = cn;
            buf[t * JS + tid] = hn;

            uint32_t ha = smem_u32(&h_full[j]);
            #pragma unroll
            for (int peer = 0; peer < CL; peer++) st_cluster(ha, peer, hn);

            out[((size_t)t * BB + b) * HH + j] = hn;
            if (t == myLen - 1) {
                out[(size_t)TT * BB * HH + (size_t)b * HH + j] = hn;
                out[(size_t)TT * BB * HH + (size_t)BB * HH + (size_t)b * HH + j] = cn;
            }
        }
        __syncthreads();
        if (tid < CL) bar_arrive_rank(bar2, tid);
        bar_wait(bar2, par);                                          // B2
    }
}

// ---------------------------------------------------------------------------
extern "C" void kernel_launch(void* const* d_in, const int* in_sizes, int n_in,
                              void* d_out, int out_size)
{
    const float* embs = (const float*)d_in[0];
    const int*   lens = (const int*)  d_in[1];
    const float* W_ih = (const float*)d_in[2];
    const float* W_hh = (const float*)d_in[3];
    const float* b_ih = (const float*)d_in[4];
    const float* b_hh = (const float*)d_in[5];
    const float* W_a  = (const float*)d_in[6];
    const float* b_a  = (const float*)d_in[7];
    float* out = (float*)d_out;

    const int smem_bytes = 51464 * (int)sizeof(float);   // ~201 KB
    cudaFuncSetAttribute(recur_kernel, cudaFuncAttributeMaxDynamicSharedMemorySize, smem_bytes);

    xproj_kernel<<<dim3((TT * BB) / 64, G4 / 64), 256>>>(embs, W_ih, b_ih, b_hh);
    recur_kernel<<<BB * CL, NTH, smem_bytes>>>(lens, W_hh, W_a, b_a, out);
}

// round 7
// speedup vs baseline: 5.2767x; 1.1835x over previous
#include <cuda_runtime.h>
#include <cstdint>
#include <math.h>

#define TT 128
#define BB 32
#define HH 256
#define II 256
#define G4 1024   // 4*H
#define CL 4      // CTAs per cluster
#define NTH 512
#define JS 64     // j-slice per rank (HH/CL)

// Scratch for hoisted input projection: xproj[t][b][row] = emb@W_ih^T + b_ih + b_hh
__device__ float g_xproj[(size_t)TT * BB * G4];  // 16 MB

// ---------------------------------------------------------------------------
// Kernel A: xproj = emb @ W_ih^T + (b_ih + b_hh)   (M=4096, N=1024, K=256)
// ---------------------------------------------------------------------------
__global__ void __launch_bounds__(256) xproj_kernel(
    const float* __restrict__ emb, const float* __restrict__ W_ih,
    const float* __restrict__ b_ih, const float* __restrict__ b_hh)
{
    __shared__ float As[64][65];
    __shared__ float Bs[64][65];
    const int K = II;
    const int bm = blockIdx.x * 64, bn = blockIdx.y * 64;
    const int tx = threadIdx.x & 15, ty = threadIdx.x >> 4;
    float acc[4][4] = {};

    for (int k0 = 0; k0 < K; k0 += 64) {
        for (int i = threadIdx.x; i < 64 * 64; i += 256) {
            int r = i >> 6, cc = i & 63;
            As[r][cc] = emb[(size_t)(bm + r) * K + k0 + cc];
            Bs[r][cc] = W_ih[(size_t)(bn + r) * K + k0 + cc];
        }
        __syncthreads();
        #pragma unroll
        for (int k = 0; k < 64; k++) {
            float a[4], bv[4];
            #pragma unroll
            for (int i = 0; i < 4; i++) a[i] = As[ty * 4 + i][k];
            #pragma unroll
            for (int j = 0; j < 4; j++) bv[j] = Bs[tx * 4 + j][k];
            #pragma unroll
            for (int i = 0; i < 4; i++)
                #pragma unroll
                for (int j = 0; j < 4; j++)
                    acc[i][j] += a[i] * bv[j];
        }
        __syncthreads();
    }
    #pragma unroll
    for (int i = 0; i < 4; i++)
        #pragma unroll
        for (int j = 0; j < 4; j++) {
            int r = bm + ty * 4 + i, cI = bn + tx * 4 + j;
            g_xproj[(size_t)r * G4 + cI] = acc[i][j] + b_ih[cI] + b_hh[cI];
        }
}

// ---------------------------------------------------------------------------
// DSMEM / mbarrier helpers (vectorized stores, no atomics)
// ---------------------------------------------------------------------------
__device__ __forceinline__ uint32_t smem_u32(const void* p) {
    return (uint32_t)__cvta_generic_to_shared(p);
}
__device__ __forceinline__ uint32_t my_rank() {
    uint32_t r;
    asm("mov.u32 %0, %%cluster_ctarank;" : "=r"(r));
    return r;
}
__device__ __forceinline__ void st_cluster4(uint32_t laddr, int rank, float4 v) {
    uint32_t ra;
    asm volatile("mapa.shared::cluster.u32 %0, %1, %2;" : "=r"(ra) : "r"(laddr), "r"(rank));
    asm volatile("st.shared::cluster.v4.f32 [%0], {%1,%2,%3,%4};"
                 :: "r"(ra), "f"(v.x), "f"(v.y), "f"(v.z), "f"(v.w) : "memory");
}
__device__ __forceinline__ void bar_arrive_rank(uint32_t lbar, int rank) {
    uint32_t ra;
    asm volatile("mapa.shared::cluster.u32 %0, %1, %2;" : "=r"(ra) : "r"(lbar), "r"(rank));
    asm volatile("mbarrier.arrive.release.cluster.shared::cluster.b64 _, [%0];"
                 :: "r"(ra) : "memory");
}
__device__ __forceinline__ void bar_wait(uint32_t lbar, uint32_t parity) {
    asm volatile(
        "{\n\t.reg .pred P;\n\t"
        "LW_%=:\n\t"
        "mbarrier.try_wait.parity.acquire.cluster.shared::cta.b64 P, [%0], %1, 0x989680;\n\t"
        "@P bra LD_%=;\n\t"
        "bra LW_%=;\n\t"
        "LD_%=:\n\t}"
        :: "r"(lbar), "r"(parity) : "memory");
}

// ---------------------------------------------------------------------------
// Kernel B: 4-CTA cluster per batch element (32 clusters = 128 CTAs).
// Rank r owns: j-slice [64r,64r+64) of h/c/history (never broadcast!),
// z-rows and hu-rows [64r,64r+64), W_a K-slice columns (K-major, SMEM),
// W_hh rows {g*256+64r+i} (streamed L2). z = W_a_ctx@h and W_a_h@h are
// computed as K-partials from the LOCAL h slice and gathered to owners
// as float4 DSMEM stores. 2 cluster barriers per step.
// ---------------------------------------------------------------------------
__global__ void __launch_bounds__(NTH, 1) __cluster_dims__(CL, 1, 1)
recur_kernel(
    const int*   __restrict__ lens,
    const float* __restrict__ W_hh,   // [1024, 256]
    const float* __restrict__ W_a,    // [256, 512]
    const float* __restrict__ b_a,    // [256]
    float* __restrict__ out)          // output[T,B,H] ++ h_fin[B,H] ++ c_fin[B,H]
{
    extern __shared__ float smf[];
    unsigned long long* mbar = (unsigned long long*)smf;   // 2 barriers
    float* wacK    = smf + 8;           // [64 kk][256 row] k-major ctx cols (64 KB)
    float* wahK    = wacK   + 16384;    // [64 kk][256 row] k-major h cols   (64 KB)
    float* zbuf    = wahK   + 16384;    // [128][64] z history, my rows      (32 KB)
    float* buf     = zbuf   + 8192;     // [128][64] h history, my j-slice   (32 KB)
    float* scp     = buf    + 8192;     // [4 src][128] score partials (gathered)
    float* zpart   = scp    + 512;      // [4 src][64]  z partials for my rows
    float* yHp     = zpart  + 256;      // [4 src][64]  W_a_h@h partials, my rows
    float* alpha   = yHp    + 256;      // [128]
    float* hu_full = alpha  + 128;      // [256] gathered combined hidden
    float* y1part  = hu_full+ 256;      // [8][64]
    float* gates   = y1part + 512;      // [256] my gate rows
    float* xps     = gates  + 256;      // [256] staged xproj slice
    float* zstage  = xps    + 256;      // [256] my z partial (all 256 rows)
    float* ystage  = zstage + 256;      // [256] my yH partial (all 256 rows)
    float* scstage = ystage + 256;      // [128] my score partials
    float* hustage = scstage+ 128;      // [64]  my hu rows
    float* h_loc   = hustage+ 64;       // [64]
    float* c_loc   = h_loc  + 64;       // [64]
    float* ba_s    = c_loc  + 64;       // [64]
    // total floats: 8+16384+16384+8192+8192+512+256+256+128+256+512+256+256
    //             + 256+256+128+64+64+64+64 = 52488  (209,952 B)

    const int tid  = threadIdx.x;
    const int warp = tid >> 5, lane = tid & 31;
    const int r    = (int)my_rank();
    const int b    = blockIdx.x / CL;
    const int myLen = lens[b];

    const uint32_t bar0 = smem_u32(&mbar[0]);
    const uint32_t bar1 = smem_u32(&mbar[1]);

    // ---- one-time: W_a K-slice (cols [64r,64r+64) of each half), k-major ----
    for (int idx = tid; idx < 64 * 256; idx += NTH) {
        int kk = idx >> 8, row = idx & 255;
        wacK[kk * 256 + row] = W_a[(size_t)row * 512 + 64 * r + kk];
        wahK[kk * 256 + row] = W_a[(size_t)row * 512 + 256 + 64 * r + kk];
    }
    if (tid < JS) ba_s[tid] = __ldg(&b_a[JS * r + tid]);
    if (tid < 256) hu_full[tid] = 0.f;
    if (tid < JS * 2) { h_loc[tid & 63] = 0.f; c_loc[tid & 63] = 0.f; }
    if (tid == 0) {
        #pragma unroll
        for (int k = 0; k < 2; k++)
            asm volatile("mbarrier.init.shared.b64 [%0], %1;"
                         :: "r"(smem_u32(&mbar[k])), "r"(CL) : "memory");
        asm volatile("fence.mbarrier_init.release.cluster;" ::: "memory");
    }
    __syncthreads();
    asm volatile("barrier.cluster.arrive.aligned;" ::: "memory");
    asm volatile("barrier.cluster.wait.aligned;" ::: "memory");

    for (int t = 0; t < TT; t++) {
        const uint32_t par = (uint32_t)(t & 1);

        // ======== P1 (all local): z/yH K-partials from h_loc; scores ========
        if (t > 0) {
            {   // 512 threads: 0-255 -> z partial, 256-511 -> yH partial
                int half = tid >> 8, row = tid & 255;
                const float* W = half ? wahK : wacK;
                float acc = 0.f;
                #pragma unroll 8
                for (int kk = 0; kk < 64; kk++)
                    acc += W[kk * 256 + row] * h_loc[kk];
                (half ? ystage : zstage)[row] = acc;
            }
            // scores: warp handles 4 s per block, 8 lanes per s
            for (int blk = warp; blk * 4 < t; blk += 16) {
                int g = lane >> 3, L = lane & 7;
                int s = blk * 4 + g;
                float acc = 0.f;
                if (s < t) {
                    float4 b0 = *(const float4*)&buf[s * 64 + L * 8];
                    float4 b1 = *(const float4*)&buf[s * 64 + L * 8 + 4];
                    float4 h0 = *(const float4*)&h_loc[L * 8];
                    float4 h1 = *(const float4*)&h_loc[L * 8 + 4];
                    acc = b0.x * h0.x + b0.y * h0.y + b0.z * h0.z + b0.w * h0.w
                        + b1.x * h1.x + b1.y * h1.y + b1.z * h1.z + b1.w * h1.w;
                }
                acc += __shfl_xor_sync(0xffffffffu, acc, 1);
                acc += __shfl_xor_sync(0xffffffffu, acc, 2);
                acc += __shfl_xor_sync(0xffffffffu, acc, 4);
                if (L == 0 && s < t) scstage[s] = acc;
            }
        }
        // stage xproj slice for my gate rows
        if (tid < 256) {
            int grow = (tid >> 6) * 256 + JS * r + (tid & 63);
            xps[tid] = __ldg(&g_xproj[((size_t)t * BB + b) * G4 + grow]);
        }
        __syncthreads();

        // ---- vectorized DSMEM pushes ----
        if (t > 0) {
            if (tid < 64) {               // z partials -> owners
                int dest = tid >> 4, q = tid & 15;
                st_cluster4(smem_u32(&zpart[r * 64 + q * 4]), dest,
                            *(const float4*)&zstage[dest * 64 + q * 4]);
            } else if (tid < 128) {       // yH partials -> owners
                int i = tid - 64, dest = i >> 4, q = i & 15;
                st_cluster4(smem_u32(&yHp[r * 64 + q * 4]), dest,
                            *(const float4*)&ystage[dest * 64 + q * 4]);
            } else if (tid < 256) {       // score partials -> all ranks
                int i = tid - 128, chunk = i >> 2, peer = i & 3;
                if (chunk * 4 < t)
                    st_cluster4(smem_u32(&scp[r * 128 + chunk * 4]), peer,
                                *(const float4*)&scstage[chunk * 4]);
            }
        }
        if (tid < CL) bar_arrive_rank(bar0, tid);
        bar_wait(bar0, par);                                          // B0

        // ======== P2: assemble z_{t-1}; softmax; y1; combine; push hu =======
        if (t > 0) {
            if (tid < 64)   // zbuf[t-1][my rows] = sum of 4 K-partials
                zbuf[(t - 1) * 64 + tid] = zpart[0 * 64 + tid] + zpart[1 * 64 + tid]
                                         + zpart[2 * 64 + tid] + zpart[3 * 64 + tid];
            if (warp == 0) {  // softmax (replicated per rank)
                float v[4];
                float m = -1e30f;
                #pragma unroll
                for (int c = 0; c < 4; c++) {
                    int s = lane + 32 * c;
                    float sum = -1e30f;
                    if (s < t)
                        sum = scp[0 * 128 + s] + scp[1 * 128 + s]
                            + scp[2 * 128 + s] + scp[3 * 128 + s];
                    v[c] = sum;
                    m = fmaxf(m, sum);
                }
                #pragma unroll
                for (int o = 16; o > 0; o >>= 1) m = fmaxf(m, __shfl_xor_sync(0xffffffffu, m, o));
                float tot = 0.f;
                #pragma unroll
                for (int c = 0; c < 4; c++) {
                    int s = lane + 32 * c;
                    if (s < t) { v[c] = __expf(v[c] - m); tot += v[c]; }
                }
                #pragma unroll
                for (int o = 16; o > 0; o >>= 1) tot += __shfl_xor_sync(0xffffffffu, tot, o);
                float inv = 1.f / tot;
                #pragma unroll
                for (int c = 0; c < 4; c++) {
                    int s = lane + 32 * c;
                    if (s < t) alpha[s] = v[c] * inv;
                }
            }
            __syncthreads();

            {   // y1 partials over s (8 groups x 64 rows)
                int g = tid >> 6, row = tid & 63;
                float acc = 0.f;
                for (int s = g; s < t; s += 8) acc += alpha[s] * zbuf[s * 64 + row];
                y1part[g * 64 + row] = acc;
            }
            __syncthreads();

            if (tid < 64) {   // hu rows = tanh(y1 + yH + b_a)
                float y = y1part[0 * 64 + tid] + y1part[1 * 64 + tid]
                        + y1part[2 * 64 + tid] + y1part[3 * 64 + tid]
                        + y1part[4 * 64 + tid] + y1part[5 * 64 + tid]
                        + y1part[6 * 64 + tid] + y1part[7 * 64 + tid]
                        + yHp[0 * 64 + tid] + yHp[1 * 64 + tid]
                        + yHp[2 * 64 + tid] + yHp[3 * 64 + tid];
                hustage[tid] = tanhf(y + ba_s[tid]);
            }
            __syncthreads();

            if (tid < 64) {   // push my hu rows to all ranks (incl. self)
                int dest = tid >> 4, q = tid & 15;
                st_cluster4(smem_u32(&hu_full[JS * r + q * 4]), dest,
                            *(const float4*)&hustage[q * 4]);
            }
        }
        if (tid < CL) bar_arrive_rank(bar1, tid);
        bar_wait(bar1, par);                                          // B1

        // ======== P3: gates GEMV, W_hh streamed (my 256 rows) ===============
        #pragma unroll
        for (int grp = 0; grp < 2; grp++) {
            int lrb = warp * 16 + grp * 8;
            float acc[8] = {0.f, 0.f, 0.f, 0.f, 0.f, 0.f, 0.f, 0.f};
            #pragma unroll
            for (int it = 0; it < 2; it++) {
                float4 x = *(const float4*)&hu_full[it * 128 + lane * 4];
                #pragma unroll
                for (int rr = 0; rr < 8; rr++) {
                    int lr = lrb + rr;
                    int grow = (lr >> 6) * 256 + JS * r + (lr & 63);
                    float4 w = __ldcg((const float4*)&W_hh[(size_t)grow * HH + it * 128 + lane * 4]);
                    acc[rr] += w.x * x.x + w.y * x.y + w.z * x.z + w.w * x.w;
                }
            }
            #pragma unroll
            for (int rr = 0; rr < 8; rr++) {
                float v = acc[rr];
                #pragma unroll
                for (int o = 16; o > 0; o >>= 1) v += __shfl_xor_sync(0xffffffffu, v, o);
                if (lane == rr) gates[lrb + rr] = v + xps[lrb + rr];
            }
        }
        __syncthreads();

        // ======== cell update on my j-slice (all local, no broadcast) =======
        if (tid < JS) {
            int j = JS * r + tid;
            float ig = gates[tid],       fg = gates[64 + tid];
            float gg = gates[128 + tid], og = gates[192 + tid];
            float si = 1.f / (1.f + __expf(-ig));
            float sf = 1.f / (1.f + __expf(-fg));
            float so = 1.f / (1.f + __expf(-og));
            float cn = sf * c_loc[tid] + si * tanhf(gg);
            float hn = so * tanhf(cn);
            c_loc[tid] = cn;
            h_loc[tid] = hn;
            buf[t * 64 + tid] = hn;

            out[((size_t)t * BB + b) * HH + j] = hn;
            if (t == myLen - 1) {
                out[(size_t)TT * BB * HH + (size_t)b * HH + j] = hn;
                out[(size_t)TT * BB * HH + (size_t)BB * HH + (size_t)b * HH + j] = cn;
            }
        }
        __syncthreads();
    }
}

// ---------------------------------------------------------------------------
extern "C" void kernel_launch(void* const* d_in, const int* in_sizes, int n_in,
                              void* d_out, int out_size)
{
    const float* embs = (const float*)d_in[0];
    const int*   lens = (const int*)  d_in[1];
    const float* W_ih = (const float*)d_in[2];
    const float* W_hh = (const float*)d_in[3];
    const float* b_ih = (const float*)d_in[4];
    const float* b_hh = (const float*)d_in[5];
    const float* W_a  = (const float*)d_in[6];
    const float* b_a  = (const float*)d_in[7];
    float* out = (float*)d_out;

    const int smem_bytes = 52488 * (int)sizeof(float);   // ~205 KB
    cudaFuncSetAttribute(recur_kernel, cudaFuncAttributeMaxDynamicSharedMemorySize, smem_bytes);

    xproj_kernel<<<dim3((TT * BB) / 64, G4 / 64), 256>>>(embs, W_ih, b_ih, b_hh);
    recur_kernel<<<BB * CL, NTH, smem_bytes>>>(lens, W_hh, W_a, b_a, out);
}

// round 8
// speedup vs baseline: 6.4639x; 1.2250x over previous
#include <cuda_runtime.h>
#include <cuda_fp16.h>
#include <cstdint>
#include <math.h>

#define TT 128
#define BB 32
#define HH 256
#define II 256
#define G4 1024   // 4*H
#define CL 4      // CTAs per cluster
#define NTH 512
#define JS 64     // j-slice per rank (HH/CL)

// Scratch: hoisted input projection xproj[t][b][row]
__device__ float g_xproj[(size_t)TT * BB * G4];       // 16 MB
// fp16 W_hh, permuted for coalesced rank-sliced streaming:
// element ((r*16 + i)*512 + t)*8 + e  =  W_hh[grow(r, t&255)][ (t>>8)*128 + i*8 + e ]
// with grow(r, lr) = (lr>>6)*256 + 64r + (lr&63)
__device__ __half g_whh16[CL * 16 * 512 * 8];         // 512 KB

// ---------------------------------------------------------------------------
// Kernel A: xproj = emb @ W_ih^T + (b_ih + b_hh)   (M=4096, N=1024, K=256)
// ---------------------------------------------------------------------------
__global__ void __launch_bounds__(256) xproj_kernel(
    const float* __restrict__ emb, const float* __restrict__ W_ih,
    const float* __restrict__ b_ih, const float* __restrict__ b_hh)
{
    __shared__ float As[64][65];
    __shared__ float Bs[64][65];
    const int K = II;
    const int bm = blockIdx.x * 64, bn = blockIdx.y * 64;
    const int tx = threadIdx.x & 15, ty = threadIdx.x >> 4;
    float acc[4][4] = {};

    for (int k0 = 0; k0 < K; k0 += 64) {
        for (int i = threadIdx.x; i < 64 * 64; i += 256) {
            int r = i >> 6, cc = i & 63;
            As[r][cc] = emb[(size_t)(bm + r) * K + k0 + cc];
            Bs[r][cc] = W_ih[(size_t)(bn + r) * K + k0 + cc];
        }
        __syncthreads();
        #pragma unroll
        for (int k = 0; k < 64; k++) {
            float a[4], bv[4];
            #pragma unroll
            for (int i = 0; i < 4; i++) a[i] = As[ty * 4 + i][k];
            #pragma unroll
            for (int j = 0; j < 4; j++) bv[j] = Bs[tx * 4 + j][k];
            #pragma unroll
            for (int i = 0; i < 4; i++)
                #pragma unroll
                for (int j = 0; j < 4; j++)
                    acc[i][j] += a[i] * bv[j];
        }
        __syncthreads();
    }
    #pragma unroll
    for (int i = 0; i < 4; i++)
        #pragma unroll
        for (int j = 0; j < 4; j++) {
            int r = bm + ty * 4 + i, cI = bn + tx * 4 + j;
            g_xproj[(size_t)r * G4 + cI] = acc[i][j] + b_ih[cI] + b_hh[cI];
        }
}

// ---------------------------------------------------------------------------
// Kernel A2: convert + permute W_hh into g_whh16
// ---------------------------------------------------------------------------
__global__ void __launch_bounds__(256) whh16_kernel(const float* __restrict__ W_hh)
{
    int idx = blockIdx.x * 256 + threadIdx.x;        // 262144 total
    int e  = idx & 7;
    int tt = (idx >> 3) & 511;
    int i  = (idx >> 12) & 15;
    int rr = idx >> 16;
    int row_local = tt & 255, khalf = tt >> 8;
    int grow = (row_local >> 6) * 256 + 64 * rr + (row_local & 63);
    int k = khalf * 128 + i * 8 + e;
    g_whh16[idx] = __float2half_rn(W_hh[(size_t)grow * HH + k]);
}

// ---------------------------------------------------------------------------
// DSMEM / mbarrier helpers (vectorized stores, no atomics)
// ---------------------------------------------------------------------------
__device__ __forceinline__ uint32_t smem_u32(const void* p) {
    return (uint32_t)__cvta_generic_to_shared(p);
}
__device__ __forceinline__ uint32_t my_rank() {
    uint32_t r;
    asm("mov.u32 %0, %%cluster_ctarank;" : "=r"(r));
    return r;
}
__device__ __forceinline__ void st_cluster4(uint32_t laddr, int rank, float4 v) {
    uint32_t ra;
    asm volatile("mapa.shared::cluster.u32 %0, %1, %2;" : "=r"(ra) : "r"(laddr), "r"(rank));
    asm volatile("st.shared::cluster.v4.f32 [%0], {%1,%2,%3,%4};"
                 :: "r"(ra), "f"(v.x), "f"(v.y), "f"(v.z), "f"(v.w) : "memory");
}
__device__ __forceinline__ void bar_arrive_rank(uint32_t lbar, int rank) {
    uint32_t ra;
    asm volatile("mapa.shared::cluster.u32 %0, %1, %2;" : "=r"(ra) : "r"(lbar), "r"(rank));
    asm volatile("mbarrier.arrive.release.cluster.shared::cluster.b64 _, [%0];"
                 :: "r"(ra) : "memory");
}
__device__ __forceinline__ void bar_wait(uint32_t lbar, uint32_t parity) {
    asm volatile(
        "{\n\t.reg .pred P;\n\t"
        "LW_%=:\n\t"
        "mbarrier.try_wait.parity.acquire.cluster.shared::cta.b64 P, [%0], %1, 0x989680;\n\t"
        "@P bra LD_%=;\n\t"
        "bra LW_%=;\n\t"
        "LD_%=:\n\t}"
        :: "r"(lbar), "r"(parity) : "memory");
}

// ---------------------------------------------------------------------------
// Kernel B: 4-CTA cluster per batch element (32 clusters = 128 CTAs).
// R7 skeleton (z-history trick, 2 barriers/step, float4 DSMEM) with:
//  - fp16 W_hh streamed via permuted coalesced layout, shuffle-free reduce
//  - P1 W_a GEMV with float4-hoisted h
// ---------------------------------------------------------------------------
__global__ void __launch_bounds__(NTH, 1) __cluster_dims__(CL, 1, 1)
recur_kernel(
    const int*   __restrict__ lens,
    const float* __restrict__ W_a,    // [256, 512]
    const float* __restrict__ b_a,    // [256]
    float* __restrict__ out)          // output[T,B,H] ++ h_fin[B,H] ++ c_fin[B,H]
{
    extern __shared__ float smf[];
    unsigned long long* mbar = (unsigned long long*)smf;   // 2 barriers
    float* wacK    = smf + 8;           // [64 kk][256 row] k-major ctx cols (64 KB)
    float* wahK    = wacK   + 16384;    // [64 kk][256 row] k-major h cols   (64 KB)
    float* zbuf    = wahK   + 16384;    // [128][64] z history, my rows      (32 KB)
    float* buf     = zbuf   + 8192;     // [128][64] h history, my j-slice   (32 KB)
    float* scp     = buf    + 8192;     // [4 src][128] score partials (gathered)
    float* zpart   = scp    + 512;      // [4 src][64]  z partials for my rows
    float* yHp     = zpart  + 256;      // [4 src][64]  W_a_h@h partials, my rows
    float* alpha   = yHp    + 256;      // [128]
    float* hu_full = alpha  + 128;      // [256] gathered combined hidden
    float* y1part  = hu_full+ 256;      // [8][64]
    float* gates   = y1part + 512;      // [256] my gate rows
    float* xps     = gates  + 256;      // [256] staged xproj slice
    float* zstage  = xps    + 256;      // [256]
    float* ystage  = zstage + 256;      // [256]
    float* scstage = ystage + 256;      // [128]
    float* hustage = scstage+ 128;      // [64]
    float* h_loc   = hustage+ 64;       // [64]
    float* c_loc   = h_loc  + 64;       // [64]
    float* ba_s    = c_loc  + 64;       // [64]
    float* gpart   = ba_s   + 64;       // [512] gate GEMV k-half partials
    // total floats: 52488 + 512 = 53000  (212,000 B)

    const int tid  = threadIdx.x;
    const int warp = tid >> 5, lane = tid & 31;
    const int r    = (int)my_rank();
    const int b    = blockIdx.x / CL;
    const int myLen = lens[b];

    const uint32_t bar0 = smem_u32(&mbar[0]);
    const uint32_t bar1 = smem_u32(&mbar[1]);

    // ---- one-time: W_a K-slice (cols [64r,64r+64) of each half), k-major ----
    for (int idx = tid; idx < 64 * 256; idx += NTH) {
        int kk = idx >> 8, row = idx & 255;
        wacK[kk * 256 + row] = W_a[(size_t)row * 512 + 64 * r + kk];
        wahK[kk * 256 + row] = W_a[(size_t)row * 512 + 256 + 64 * r + kk];
    }
    if (tid < JS) ba_s[tid] = __ldg(&b_a[JS * r + tid]);
    if (tid < 256) hu_full[tid] = 0.f;
    if (tid < JS * 2) { h_loc[tid & 63] = 0.f; c_loc[tid & 63] = 0.f; }
    if (tid == 0) {
        #pragma unroll
        for (int k = 0; k < 2; k++)
            asm volatile("mbarrier.init.shared.b64 [%0], %1;"
                         :: "r"(smem_u32(&mbar[k])), "r"(CL) : "memory");
        asm volatile("fence.mbarrier_init.release.cluster;" ::: "memory");
    }
    __syncthreads();
    asm volatile("barrier.cluster.arrive.aligned;" ::: "memory");
    asm volatile("barrier.cluster.wait.aligned;" ::: "memory");

    // my fp16 W_hh stream base: thread t covers (khalf=t>>8, local row=t&255)
    const uint4* Wp = ((const uint4*)g_whh16) + r * (16 * 512) + tid;
    const int khalf = tid >> 8;

    for (int t = 0; t < TT; t++) {
        const uint32_t par = (uint32_t)(t & 1);

        // ======== P1 (all local): z/yH K-partials from h_loc; scores ========
        if (t > 0) {
            {   // 512 threads: 0-255 -> z partial, 256-511 -> yH partial
                int half = tid >> 8, row = tid & 255;
                const float* W = half ? wahK : wacK;
                float acc = 0.f;
                #pragma unroll
                for (int k4 = 0; k4 < 16; k4++) {
                    float4 h4 = *(const float4*)&h_loc[k4 * 4];
                    acc += W[(k4 * 4 + 0) * 256 + row] * h4.x
                         + W[(k4 * 4 + 1) * 256 + row] * h4.y
                         + W[(k4 * 4 + 2) * 256 + row] * h4.z
                         + W[(k4 * 4 + 3) * 256 + row] * h4.w;
                }
                (half ? ystage : zstage)[row] = acc;
            }
            // scores: warp handles 4 s per block, 8 lanes per s
            for (int blk = warp; blk * 4 < t; blk += 16) {
                int g = lane >> 3, L = lane & 7;
                int s = blk * 4 + g;
                float acc = 0.f;
                if (s < t) {
                    float4 b0 = *(const float4*)&buf[s * 64 + L * 8];
                    float4 b1 = *(const float4*)&buf[s * 64 + L * 8 + 4];
                    float4 h0 = *(const float4*)&h_loc[L * 8];
                    float4 h1 = *(const float4*)&h_loc[L * 8 + 4];
                    acc = b0.x * h0.x + b0.y * h0.y + b0.z * h0.z + b0.w * h0.w
                        + b1.x * h1.x + b1.y * h1.y + b1.z * h1.z + b1.w * h1.w;
                }
                acc += __shfl_xor_sync(0xffffffffu, acc, 1);
                acc += __shfl_xor_sync(0xffffffffu, acc, 2);
                acc += __shfl_xor_sync(0xffffffffu, acc, 4);
                if (L == 0 && s < t) scstage[s] = acc;
            }
        }
        // stage xproj slice for my gate rows
        if (tid < 256) {
            int grow = (tid >> 6) * 256 + JS * r + (tid & 63);
            xps[tid] = __ldg(&g_xproj[((size_t)t * BB + b) * G4 + grow]);
        }
        __syncthreads();

        // ---- vectorized DSMEM pushes ----
        if (t > 0) {
            if (tid < 64) {               // z partials -> owners
                int dest = tid >> 4, q = tid & 15;
                st_cluster4(smem_u32(&zpart[r * 64 + q * 4]), dest,
                            *(const float4*)&zstage[dest * 64 + q * 4]);
            } else if (tid < 128) {       // yH partials -> owners
                int i = tid - 64, dest = i >> 4, q = i & 15;
                st_cluster4(smem_u32(&yHp[r * 64 + q * 4]), dest,
                            *(const float4*)&ystage[dest * 64 + q * 4]);
            } else if (tid < 256) {       // score partials -> all ranks
                int i = tid - 128, chunk = i >> 2, peer = i & 3;
                if (chunk * 4 < t)
                    st_cluster4(smem_u32(&scp[r * 128 + chunk * 4]), peer,
                                *(const float4*)&scstage[chunk * 4]);
            }
        }
        if (tid < CL) bar_arrive_rank(bar0, tid);
        bar_wait(bar0, par);                                          // B0

        // ======== P2: assemble z_{t-1}; softmax; y1; combine; push hu =======
        if (t > 0) {
            if (tid < 64)   // zbuf[t-1][my rows] = sum of 4 K-partials
                zbuf[(t - 1) * 64 + tid] = zpart[0 * 64 + tid] + zpart[1 * 64 + tid]
                                         + zpart[2 * 64 + tid] + zpart[3 * 64 + tid];
            if (warp == 0) {  // softmax (replicated per rank)
                float v[4];
                float m = -1e30f;
                #pragma unroll
                for (int c = 0; c < 4; c++) {
                    int s = lane + 32 * c;
                    float sum = -1e30f;
                    if (s < t)
                        sum = scp[0 * 128 + s] + scp[1 * 128 + s]
                            + scp[2 * 128 + s] + scp[3 * 128 + s];
                    v[c] = sum;
                    m = fmaxf(m, sum);
                }
                #pragma unroll
                for (int o = 16; o > 0; o >>= 1) m = fmaxf(m, __shfl_xor_sync(0xffffffffu, m, o));
                float tot = 0.f;
                #pragma unroll
                for (int c = 0; c < 4; c++) {
                    int s = lane + 32 * c;
                    if (s < t) { v[c] = __expf(v[c] - m); tot += v[c]; }
                }
                #pragma unroll
                for (int o = 16; o > 0; o >>= 1) tot += __shfl_xor_sync(0xffffffffu, tot, o);
                float inv = 1.f / tot;
                #pragma unroll
                for (int c = 0; c < 4; c++) {
                    int s = lane + 32 * c;
                    if (s < t) alpha[s] = v[c] * inv;
                }
            }
            __syncthreads();

            {   // y1 partials over s (8 groups x 64 rows)
                int g = tid >> 6, row = tid & 63;
                float acc = 0.f;
                for (int s = g; s < t; s += 8) acc += alpha[s] * zbuf[s * 64 + row];
                y1part[g * 64 + row] = acc;
            }
            __syncthreads();

            if (tid < 64) {   // hu rows = tanh(y1 + yH + b_a)
                float y = y1part[0 * 64 + tid] + y1part[1 * 64 + tid]
                        + y1part[2 * 64 + tid] + y1part[3 * 64 + tid]
                        + y1part[4 * 64 + tid] + y1part[5 * 64 + tid]
                        + y1part[6 * 64 + tid] + y1part[7 * 64 + tid]
                        + yHp[0 * 64 + tid] + yHp[1 * 64 + tid]
                        + yHp[2 * 64 + tid] + yHp[3 * 64 + tid];
                hustage[tid] = tanhf(y + ba_s[tid]);
            }
            __syncthreads();

            if (tid < 64) {   // push my hu rows to all ranks (incl. self)
                int dest = tid >> 4, q = tid & 15;
                st_cluster4(smem_u32(&hu_full[JS * r + q * 4]), dest,
                            *(const float4*)&hustage[q * 4]);
            }
        }
        if (tid < CL) bar_arrive_rank(bar1, tid);
        bar_wait(bar1, par);                                          // B1

        // ======== P3: gates GEMV, fp16 W_hh streamed, shuffle-free ==========
        {
            float acc = 0.f;
            #pragma unroll
            for (int i = 0; i < 16; i++) {
                uint4 w = __ldcg(Wp + i * 512);
                float4 x0 = *(const float4*)&hu_full[khalf * 128 + i * 8];
                float4 x1 = *(const float4*)&hu_full[khalf * 128 + i * 8 + 4];
                float2 f01 = __half22float2(*reinterpret_cast<__half2*>(&w.x));
                float2 f23 = __half22float2(*reinterpret_cast<__half2*>(&w.y));
                float2 f45 = __half22float2(*reinterpret_cast<__half2*>(&w.z));
                float2 f67 = __half22float2(*reinterpret_cast<__half2*>(&w.w));
                acc += f01.x * x0.x + f01.y * x0.y + f23.x * x0.z + f23.y * x0.w
                     + f45.x * x1.x + f45.y * x1.y + f67.x * x1.z + f67.y * x1.w;
            }
            gpart[tid] = acc;
        }
        __syncthreads();
        if (tid < 256) gates[tid] = gpart[tid] + gpart[tid + 256] + xps[tid];
        __syncthreads();

        // ======== cell update on my j-slice (all local) =====================
        if (tid < JS) {
            int j = JS * r + tid;
            float ig = gates[tid],       fg = gates[64 + tid];
            float gg = gates[128 + tid], og = gates[192 + tid];
            float si = 1.f / (1.f + __expf(-ig));
            float sf = 1.f / (1.f + __expf(-fg));
            float so = 1.f / (1.f + __expf(-og));
            float cn = sf * c_loc[tid] + si * tanhf(gg);
            float hn = so * tanhf(cn);
            c_loc[tid] = cn;
            h_loc[tid] = hn;
            buf[t * 64 + tid] = hn;

            out[((size_t)t * BB + b) * HH + j] = hn;
            if (t == myLen - 1) {
                out[(size_t)TT * BB * HH + (size_t)b * HH + j] = hn;
                out[(size_t)TT * BB * HH + (size_t)BB * HH + (size_t)b * HH + j] = cn;
            }
        }
        __syncthreads();
    }
}

// ---------------------------------------------------------------------------
extern "C" void kernel_launch(void* const* d_in, const int* in_sizes, int n_in,
                              void* d_out, int out_size)
{
    const float* embs = (const float*)d_in[0];
    const int*   lens = (const int*)  d_in[1];
    const float* W_ih = (const float*)d_in[2];
    const float* W_hh = (const float*)d_in[3];
    const float* b_ih = (const float*)d_in[4];
    const float* b_hh = (const float*)d_in[5];
    const float* W_a  = (const float*)d_in[6];
    const float* b_a  = (const float*)d_in[7];
    float* out = (float*)d_out;

    const int smem_bytes = 53000 * (int)sizeof(float);   // ~207 KB
    cudaFuncSetAttribute(recur_kernel, cudaFuncAttributeMaxDynamicSharedMemorySize, smem_bytes);

    whh16_kernel<<<1024, 256>>>(W_hh);
    xproj_kernel<<<dim3((TT * BB) / 64, G4 / 64), 256>>>(embs, W_ih, b_ih, b_hh);
    recur_kernel<<<BB * CL, NTH, smem_bytes>>>(lens, W_a, b_a, out);
}

// round 10
// speedup vs baseline: 7.1353x; 1.1039x over previous
#include <cuda_runtime.h>
#include <cuda_fp16.h>
#include <cstdint>
#include <math.h>

#define TT 128
#define BB 32
#define HH 256
#define II 256
#define G4 1024   // 4*H
#define CL 4      // CTAs per cluster
#define NTH 512
#define JS 64     // j-slice per rank (HH/CL)

// Scratch: hoisted input projection xproj[t][b][row]
__device__ float g_xproj[(size_t)TT * BB * G4];       // 16 MB
// fp16 W_hh, permuted per rank into two k-halves:
//   uint4 index ((r*2 + part)*16 + i)*256 + row  holds halves e=0..7 of
//   W_hh[grow(r,row)][part*128 + i*8 + e],  grow(r,row)=(row>>6)*256+64r+(row&63)
__device__ __half g_whh16[CL * 2 * 16 * 256 * 8];     // 512 KB

// ---------------------------------------------------------------------------
// Kernel A: xproj = emb @ W_ih^T + (b_ih + b_hh)   (M=4096, N=1024, K=256)
// ---------------------------------------------------------------------------
__global__ void __launch_bounds__(256) xproj_kernel(
    const float* __restrict__ emb, const float* __restrict__ W_ih,
    const float* __restrict__ b_ih, const float* __restrict__ b_hh)
{
    __shared__ float As[64][65];
    __shared__ float Bs[64][65];
    const int K = II;
    const int bm = blockIdx.x * 64, bn = blockIdx.y * 64;
    const int tx = threadIdx.x & 15, ty = threadIdx.x >> 4;
    float acc[4][4] = {};

    for (int k0 = 0; k0 < K; k0 += 64) {
        for (int i = threadIdx.x; i < 64 * 64; i += 256) {
            int r = i >> 6, cc = i & 63;
            As[r][cc] = emb[(size_t)(bm + r) * K + k0 + cc];
            Bs[r][cc] = W_ih[(size_t)(bn + r) * K + k0 + cc];
        }
        __syncthreads();
        #pragma unroll
        for (int k = 0; k < 64; k++) {
            float a[4], bv[4];
            #pragma unroll
            for (int i = 0; i < 4; i++) a[i] = As[ty * 4 + i][k];
            #pragma unroll
            for (int j = 0; j < 4; j++) bv[j] = Bs[tx * 4 + j][k];
            #pragma unroll
            for (int i = 0; i < 4; i++)
                #pragma unroll
                for (int j = 0; j < 4; j++)
                    acc[i][j] += a[i] * bv[j];
        }
        __syncthreads();
    }
    #pragma unroll
    for (int i = 0; i < 4; i++)
        #pragma unroll
        for (int j = 0; j < 4; j++) {
            int r = bm + ty * 4 + i, cI = bn + tx * 4 + j;
            g_xproj[(size_t)r * G4 + cI] = acc[i][j] + b_ih[cI] + b_hh[cI];
        }
}

// ---------------------------------------------------------------------------
// Kernel A2: convert + permute W_hh into g_whh16 (two k-halves per rank)
// ---------------------------------------------------------------------------
__global__ void __launch_bounds__(256) whh16_kernel(const float* __restrict__ W_hh)
{
    int idx = blockIdx.x * 256 + threadIdx.x;        // 262144 total halves
    int e    = idx & 7;
    int row  = (idx >> 3) & 255;
    int i    = (idx >> 11) & 15;
    int part = (idx >> 15) & 1;
    int rr   = idx >> 16;
    int grow = (row >> 6) * 256 + 64 * rr + (row & 63);
    int k    = part * 128 + i * 8 + e;
    g_whh16[idx] = __float2half_rn(W_hh[(size_t)grow * HH + k]);
}

// ---------------------------------------------------------------------------
// DSMEM / mbarrier helpers (vectorized stores, no atomics)
// ---------------------------------------------------------------------------
__device__ __forceinline__ uint32_t smem_u32(const void* p) {
    return (uint32_t)__cvta_generic_to_shared(p);
}
__device__ __forceinline__ uint32_t my_rank() {
    uint32_t r;
    asm("mov.u32 %0, %%cluster_ctarank;" : "=r"(r));
    return r;
}
__device__ __forceinline__ void st_cluster4(uint32_t laddr, int rank, float4 v) {
    uint32_t ra;
    asm volatile("mapa.shared::cluster.u32 %0, %1, %2;" : "=r"(ra) : "r"(laddr), "r"(rank));
    asm volatile("st.shared::cluster.v4.f32 [%0], {%1,%2,%3,%4};"
                 :: "r"(ra), "f"(v.x), "f"(v.y), "f"(v.z), "f"(v.w) : "memory");
}
__device__ __forceinline__ void bar_arrive_rank(uint32_t lbar, int rank) {
    uint32_t ra;
    asm volatile("mapa.shared::cluster.u32 %0, %1, %2;" : "=r"(ra) : "r"(lbar), "r"(rank));
    asm volatile("mbarrier.arrive.release.cluster.shared::cluster.b64 _, [%0];"
                 :: "r"(ra) : "memory");
}
__device__ __forceinline__ void bar_wait(uint32_t lbar, uint32_t parity) {
    asm volatile(
        "{\n\t.reg .pred P;\n\t"
        "LW_%=:\n\t"
        "mbarrier.try_wait.parity.acquire.cluster.shared::cta.b64 P, [%0], %1, 0x989680;\n\t"
        "@P bra LD_%=;\n\t"
        "bra LW_%=;\n\t"
        "LD_%=:\n\t}"
        :: "r"(lbar), "r"(parity) : "memory");
}

// dot of 8 fp16 weights (uint4) with 8 fp32 x values (two float4), fp32 accum
__device__ __forceinline__ float dot8h(uint4 w, float4 xa, float4 xb) {
    __half2* hw = reinterpret_cast<__half2*>(&w);
    float2 f0 = __half22float2(hw[0]);
    float2 f1 = __half22float2(hw[1]);
    float2 f2 = __half22float2(hw[2]);
    float2 f3 = __half22float2(hw[3]);
    return f0.x * xa.x + f0.y * xa.y + f1.x * xa.z + f1.y * xa.w
         + f2.x * xb.x + f2.y * xb.y + f3.x * xb.z + f3.y * xb.w;
}

// ---------------------------------------------------------------------------
// Kernel B: 4-CTA cluster per batch element (32 clusters = 128 CTAs).
// R8 skeleton with: fp16 W_a SMEM-resident (halved crossbar bytes) and
// fp16 W_hh k-lo half SMEM-resident + k-hi half streamed (halved L2 bytes).
// ---------------------------------------------------------------------------
__global__ void __launch_bounds__(NTH, 1) __cluster_dims__(CL, 1, 1)
recur_kernel(
    const int*   __restrict__ lens,
    const float* __restrict__ W_a,    // [256, 512]
    const float* __restrict__ b_a,    // [256]
    float* __restrict__ out)          // output[T,B,H] ++ h_fin[B,H] ++ c_fin[B,H]
{
    extern __shared__ float smf[];
    unsigned long long* mbar = (unsigned long long*)smf;   // 2 barriers
    float* waH_f   = smf + 8;           // 32768 halves: [hs][k8][row][e]  (64 KB)
    float* whhS_f  = waH_f  + 16384;    // 32768 halves: k[0:128] slice    (64 KB)
    float* zbuf    = whhS_f + 16384;    // [128][64] z history, my rows    (32 KB)
    float* buf     = zbuf   + 8192;     // [128][64] h history, my j-slice (32 KB)
    float* scp     = buf    + 8192;     // [4 src][128] score partials
    float* zpart   = scp    + 512;      // [4 src][64]
    float* yHp     = zpart  + 256;      // [4 src][64]
    float* alpha   = yHp    + 256;      // [128]
    float* hu_full = alpha  + 128;      // [256]
    float* y1part  = hu_full+ 256;      // [8][64]
    float* gates   = y1part + 512;      // [256]
    float* xps     = gates  + 256;      // [256]
    float* zstage  = xps    + 256;      // [256]
    float* ystage  = zstage + 256;      // [256]
    float* scstage = ystage + 256;      // [128]
    float* hustage = scstage+ 128;      // [64]
    float* h_loc   = hustage+ 64;       // [64]
    float* c_loc   = h_loc  + 64;       // [64]
    float* ba_s    = c_loc  + 64;       // [64]
    float* gpart   = ba_s   + 64;       // [512]
    // total: 53000 floats = 212,000 B (gpart ends at 53000)

    __half* waH  = (__half*)waH_f;
    uint4*  waU  = (uint4*)waH_f;
    uint4*  whhS = (uint4*)whhS_f;

    const int tid  = threadIdx.x;
    const int warp = tid >> 5, lane = tid & 31;
    const int r    = (int)my_rank();
    const int b    = blockIdx.x / CL;
    const int myLen = lens[b];

    const uint32_t bar0 = smem_u32(&mbar[0]);
    const uint32_t bar1 = smem_u32(&mbar[1]);

    // ---- one-time: W_a K-slice -> fp16 SMEM, [hs][k8][row][e] layout ----
    for (int idx = tid; idx < 32768; idx += NTH) {
        int e = idx & 7, row = (idx >> 3) & 255, k8 = (idx >> 11) & 7, hs = idx >> 14;
        int col = hs * 256 + 64 * r + k8 * 8 + e;
        waH[idx] = __float2half_rn(W_a[(size_t)row * 512 + col]);
    }
    // ---- one-time: W_hh k-lo half -> SMEM (4096 uint4) ----
    {
        const uint4* src = (const uint4*)g_whh16 + (r * 2 + 0) * 4096;
        for (int i = tid; i < 4096; i += NTH) whhS[i] = __ldcg(&src[i]);
    }
    if (tid < JS) ba_s[tid] = __ldg(&b_a[JS * r + tid]);
    if (tid < 256) hu_full[tid] = 0.f;
    if (tid < JS * 2) { h_loc[tid & 63] = 0.f; c_loc[tid & 63] = 0.f; }
    if (tid == 0) {
        #pragma unroll
        for (int k = 0; k < 2; k++)
            asm volatile("mbarrier.init.shared.b64 [%0], %1;"
                         :: "r"(smem_u32(&mbar[k])), "r"(CL) : "memory");
        asm volatile("fence.mbarrier_init.release.cluster;" ::: "memory");
    }
    __syncthreads();
    asm volatile("barrier.cluster.arrive.aligned;" ::: "memory");
    asm volatile("barrier.cluster.wait.aligned;" ::: "memory");

    // streamed W_hh k-hi half base: thread covers row = tid&255 when tid>=256
    const uint4* WpHi = (const uint4*)g_whh16 + (r * 2 + 1) * 4096 + (tid & 255);

    for (int t = 0; t < TT; t++) {
        const uint32_t par = (uint32_t)(t & 1);

        // ======== P1 (all local): z/yH K-partials from h_loc; scores ========
        if (t > 0) {
            {   // 512 threads: hs=0 -> z partial (ctx cols), hs=1 -> yH partial
                int hs = tid >> 8, row = tid & 255;
                const uint4* W = waU + hs * 2048 + row;
                const float4* h4 = (const float4*)h_loc;
                float acc = 0.f;
                #pragma unroll
                for (int k8 = 0; k8 < 8; k8++)
                    acc += dot8h(W[k8 * 256], h4[k8 * 2], h4[k8 * 2 + 1]);
                (hs ? ystage : zstage)[row] = acc;
            }
            // scores: warp handles 4 s per block, 8 lanes per s
            for (int blk = warp; blk * 4 < t; blk += 16) {
                int g = lane >> 3, L = lane & 7;
                int s = blk * 4 + g;
                float acc = 0.f;
                if (s < t) {
                    float4 b0 = *(const float4*)&buf[s * 64 + L * 8];
                    float4 b1 = *(const float4*)&buf[s * 64 + L * 8 + 4];
                    float4 h0 = *(const float4*)&h_loc[L * 8];
                    float4 h1 = *(const float4*)&h_loc[L * 8 + 4];
                    acc = b0.x * h0.x + b0.y * h0.y + b0.z * h0.z + b0.w * h0.w
                        + b1.x * h1.x + b1.y * h1.y + b1.z * h1.z + b1.w * h1.w;
                }
                acc += __shfl_xor_sync(0xffffffffu, acc, 1);
                acc += __shfl_xor_sync(0xffffffffu, acc, 2);
                acc += __shfl_xor_sync(0xffffffffu, acc, 4);
                if (L == 0 && s < t) scstage[s] = acc;
            }
        }
        // stage xproj slice for my gate rows
        if (tid < 256) {
            int grow = (tid >> 6) * 256 + JS * r + (tid & 63);
            xps[tid] = __ldg(&g_xproj[((size_t)t * BB + b) * G4 + grow]);
        }
        __syncthreads();

        // ---- vectorized DSMEM pushes ----
        if (t > 0) {
            if (tid < 64) {               // z partials -> owners
                int dest = tid >> 4, q = tid & 15;
                st_cluster4(smem_u32(&zpart[r * 64 + q * 4]), dest,
                            *(const float4*)&zstage[dest * 64 + q * 4]);
            } else if (tid < 128) {       // yH partials -> owners
                int i = tid - 64, dest = i >> 4, q = i & 15;
                st_cluster4(smem_u32(&yHp[r * 64 + q * 4]), dest,
                            *(const float4*)&ystage[dest * 64 + q * 4]);
            } else if (tid < 256) {       // score partials -> all ranks
                int i = tid - 128, chunk = i >> 2, peer = i & 3;
                if (chunk * 4 < t)
                    st_cluster4(smem_u32(&scp[r * 128 + chunk * 4]), peer,
                                *(const float4*)&scstage[chunk * 4]);
            }
        }
        if (tid < CL) bar_arrive_rank(bar0, tid);
        bar_wait(bar0, par);                                          // B0

        // ======== P2: assemble z_{t-1}; softmax; y1; combine; push hu =======
        if (t > 0) {
            if (tid < 64)
                zbuf[(t - 1) * 64 + tid] = zpart[0 * 64 + tid] + zpart[1 * 64 + tid]
                                         + zpart[2 * 64 + tid] + zpart[3 * 64 + tid];
            if (warp == 0) {
                float v[4];
                float m = -1e30f;
                #pragma unroll
                for (int c = 0; c < 4; c++) {
                    int s = lane + 32 * c;
                    float sum = -1e30f;
                    if (s < t)
                        sum = scp[0 * 128 + s] + scp[1 * 128 + s]
                            + scp[2 * 128 + s] + scp[3 * 128 + s];
                    v[c] = sum;
                    m = fmaxf(m, sum);
                }
                #pragma unroll
                for (int o = 16; o > 0; o >>= 1) m = fmaxf(m, __shfl_xor_sync(0xffffffffu, m, o));
                float tot = 0.f;
                #pragma unroll
                for (int c = 0; c < 4; c++) {
                    int s = lane + 32 * c;
                    if (s < t) { v[c] = __expf(v[c] - m); tot += v[c]; }
                }
                #pragma unroll
                for (int o = 16; o > 0; o >>= 1) tot += __shfl_xor_sync(0xffffffffu, tot, o);
                float inv = 1.f / tot;
                #pragma unroll
                for (int c = 0; c < 4; c++) {
                    int s = lane + 32 * c;
                    if (s < t) alpha[s] = v[c] * inv;
                }
            }
            __syncthreads();

            {   // y1 partials over s (8 groups x 64 rows)
                int g = tid >> 6, row = tid & 63;
                float acc = 0.f;
                for (int s = g; s < t; s += 8) acc += alpha[s] * zbuf[s * 64 + row];
                y1part[g * 64 + row] = acc;
            }
            __syncthreads();

            if (tid < 64) {
                float y = y1part[0 * 64 + tid] + y1part[1 * 64 + tid]
                        + y1part[2 * 64 + tid] + y1part[3 * 64 + tid]
                        + y1part[4 * 64 + tid] + y1part[5 * 64 + tid]
                        + y1part[6 * 64 + tid] + y1part[7 * 64 + tid]
                        + yHp[0 * 64 + tid] + yHp[1 * 64 + tid]
                        + yHp[2 * 64 + tid] + yHp[3 * 64 + tid];
                hustage[tid] = tanhf(y + ba_s[tid]);
            }
            __syncthreads();

            if (tid < 64) {
                int dest = tid >> 4, q = tid & 15;
                st_cluster4(smem_u32(&hu_full[JS * r + q * 4]), dest,
                            *(const float4*)&hustage[q * 4]);
            }
        }
        if (tid < CL) bar_arrive_rank(bar1, tid);
        bar_wait(bar1, par);                                          // B1

        // ======== P3: gates GEMV; k-lo from SMEM, k-hi streamed =============
        {
            int hs = tid >> 8, row = tid & 255;
            const float4* x4 = (const float4*)&hu_full[hs * 128];
            float acc = 0.f;
            if (hs == 0) {
                const uint4* W = whhS + row;
                #pragma unroll
                for (int i = 0; i < 16; i++)
                    acc += dot8h(W[i * 256], x4[i * 2], x4[i * 2 + 1]);
            } else {
                #pragma unroll
                for (int i = 0; i < 16; i++)
                    acc += dot8h(__ldcg(WpHi + i * 256), x4[i * 2], x4[i * 2 + 1]);
            }
            gpart[tid] = acc;
        }
        __syncthreads();
        if (tid < 256) gates[tid] = gpart[tid] + gpart[tid + 256] + xps[tid];
        __syncthreads();

        // ======== cell update on my j-slice (all local) =====================
        if (tid < JS) {
            int j = JS * r + tid;
            float ig = gates[tid],       fg = gates[64 + tid];
            float gg = gates[128 + tid], og = gates[192 + tid];
            float si = 1.f / (1.f + __expf(-ig));
            float sf = 1.f / (1.f + __expf(-fg));
            float so = 1.f / (1.f + __expf(-og));
            float cn = sf * c_loc[tid] + si * tanhf(gg);
            float hn = so * tanhf(cn);
            c_loc[tid] = cn;
            h_loc[tid] = hn;
            buf[t * 64 + tid] = hn;

            out[((size_t)t * BB + b) * HH + j] = hn;
            if (t == myLen - 1) {
                out[(size_t)TT * BB * HH + (size_t)b * HH + j] = hn;
                out[(size_t)TT * BB * HH + (size_t)BB * HH + (size_t)b * HH + j] = cn;
            }
        }
        __syncthreads();
    }
}

// ---------------------------------------------------------------------------
extern "C" void kernel_launch(void* const* d_in, const int* in_sizes, int n_in,
                              void* d_out, int out_size)
{
    const float* embs = (const float*)d_in[0];
    const int*   lens = (const int*)  d_in[1];
    const float* W_ih = (const float*)d_in[2];
    const float* W_hh = (const float*)d_in[3];
    const float* b_ih = (const float*)d_in[4];
    const float* b_hh = (const float*)d_in[5];
    const float* W_a  = (const float*)d_in[6];
    const float* b_a  = (const float*)d_in[7];
    float* out = (float*)d_out;

    const int smem_bytes = 53000 * (int)sizeof(float);   // 212,000 B (fixed)
    cudaFuncSetAttribute(recur_kernel, cudaFuncAttributeMaxDynamicSharedMemorySize, smem_bytes);

    whh16_kernel<<<1024, 256>>>(W_hh);
    xproj_kernel<<<dim3((TT * BB) / 64, G4 / 64), 256>>>(embs, W_ih, b_ih, b_hh);
    recur_kernel<<<BB * CL, NTH, smem_bytes>>>(lens, W_a, b_a, out);
}

// round 12
// speedup vs baseline: 7.1822x; 1.0066x over previous
#include <cuda_runtime.h>
#include <cuda_fp16.h>
#include <cstdint>
#include <math.h>

#define TT 128
#define BB 32
#define HH 256
#define II 256
#define G4 1024   // 4*H
#define CL 4      // CTAs per cluster
#define NTH 512
#define JS 64     // j-slice per rank (HH/CL)

// ---- SMEM layout sizes (floats) — single source of truth ------------------
#define SZ_MBAR    8
#define SZ_WAZ     16384
#define SZ_WHHS    16384
#define SZ_ZBUF    8192
#define SZ_BUF     8192
#define SZ_SCP     512
#define SZ_ALPHA   128
#define SZ_HFULL   256
#define SZ_HUFULL  256
#define SZ_Y1PART  512
#define SZ_YHLOC   64
#define SZ_XPS     256
#define SZ_SCSTG   128
#define SZ_HLOC    64
#define SZ_CLOC    64
#define SZ_BAS     64
#define SZ_GPART   512
#define SMEM_FLOATS (SZ_MBAR + SZ_WAZ + SZ_WHHS + SZ_ZBUF + SZ_BUF + SZ_SCP \
                   + SZ_ALPHA + SZ_HFULL + SZ_HUFULL + SZ_Y1PART + SZ_YHLOC \
                   + SZ_XPS + SZ_SCSTG + SZ_HLOC + SZ_CLOC + SZ_BAS + SZ_GPART)
// = 51976 floats = 207,904 B

// Scratch: hoisted input projection xproj[t][b][row]
__device__ float g_xproj[(size_t)TT * BB * G4];       // 16 MB
// fp16 W_hh, permuted per rank into two k-halves (see whh16_kernel)
__device__ __half g_whh16[CL * 2 * 16 * 256 * 8];     // 512 KB

// ---------------------------------------------------------------------------
// Kernel A: xproj = emb @ W_ih^T + (b_ih + b_hh)   (M=4096, N=1024, K=256)
// ---------------------------------------------------------------------------
__global__ void __launch_bounds__(256) xproj_kernel(
    const float* __restrict__ emb, const float* __restrict__ W_ih,
    const float* __restrict__ b_ih, const float* __restrict__ b_hh)
{
    __shared__ float As[64][65];
    __shared__ float Bs[64][65];
    const int K = II;
    const int bm = blockIdx.x * 64, bn = blockIdx.y * 64;
    const int tx = threadIdx.x & 15, ty = threadIdx.x >> 4;
    float acc[4][4] = {};

    for (int k0 = 0; k0 < K; k0 += 64) {
        for (int i = threadIdx.x; i < 64 * 64; i += 256) {
            int r = i >> 6, cc = i & 63;
            As[r][cc] = emb[(size_t)(bm + r) * K + k0 + cc];
            Bs[r][cc] = W_ih[(size_t)(bn + r) * K + k0 + cc];
        }
        __syncthreads();
        #pragma unroll
        for (int k = 0; k < 64; k++) {
            float a[4], bv[4];
            #pragma unroll
            for (int i = 0; i < 4; i++) a[i] = As[ty * 4 + i][k];
            #pragma unroll
            for (int j = 0; j < 4; j++) bv[j] = Bs[tx * 4 + j][k];
            #pragma unroll
            for (int i = 0; i < 4; i++)
                #pragma unroll
                for (int j = 0; j < 4; j++)
                    acc[i][j] += a[i] * bv[j];
        }
        __syncthreads();
    }
    #pragma unroll
    for (int i = 0; i < 4; i++)
        #pragma unroll
        for (int j = 0; j < 4; j++) {
            int r = bm + ty * 4 + i, cI = bn + tx * 4 + j;
            g_xproj[(size_t)r * G4 + cI] = acc[i][j] + b_ih[cI] + b_hh[cI];
        }
}

// ---------------------------------------------------------------------------
// Kernel A2: convert + permute W_hh into g_whh16 (two k-halves per rank)
// ---------------------------------------------------------------------------
__global__ void __launch_bounds__(256) whh16_kernel(const float* __restrict__ W_hh)
{
    int idx = blockIdx.x * 256 + threadIdx.x;        // 262144 total halves
    int e    = idx & 7;
    int row  = (idx >> 3) & 255;
    int i    = (idx >> 11) & 15;
    int part = (idx >> 15) & 1;
    int rr   = idx >> 16;
    int grow = (row >> 6) * 256 + 64 * rr + (row & 63);
    int k    = part * 128 + i * 8 + e;
    g_whh16[idx] = __float2half_rn(W_hh[(size_t)grow * HH + k]);
}

// ---------------------------------------------------------------------------
// DSMEM / mbarrier helpers (vectorized stores, no atomics)
// ---------------------------------------------------------------------------
__device__ __forceinline__ uint32_t smem_u32(const void* p) {
    return (uint32_t)__cvta_generic_to_shared(p);
}
__device__ __forceinline__ uint32_t my_rank() {
    uint32_t r;
    asm("mov.u32 %0, %%cluster_ctarank;" : "=r"(r));
    return r;
}
__device__ __forceinline__ void st_cluster4(uint32_t laddr, int rank, float4 v) {
    uint32_t ra;
    asm volatile("mapa.shared::cluster.u32 %0, %1, %2;" : "=r"(ra) : "r"(laddr), "r"(rank));
    asm volatile("st.shared::cluster.v4.f32 [%0], {%1,%2,%3,%4};"
                 :: "r"(ra), "f"(v.x), "f"(v.y), "f"(v.z), "f"(v.w) : "memory");
}
__device__ __forceinline__ void bar_arrive_rank(uint32_t lbar, int rank) {
    uint32_t ra;
    asm volatile("mapa.shared::cluster.u32 %0, %1, %2;" : "=r"(ra) : "r"(lbar), "r"(rank));
    asm volatile("mbarrier.arrive.release.cluster.shared::cluster.b64 _, [%0];"
                 :: "r"(ra) : "memory");
}
__device__ __forceinline__ void bar_wait(uint32_t lbar, uint32_t parity) {
    asm volatile(
        "{\n\t.reg .pred P;\n\t"
        "LW_%=:\n\t"
        "mbarrier.try_wait.parity.acquire.cluster.shared::cta.b64 P, [%0], %1, 0x989680;\n\t"
        "@P bra LD_%=;\n\t"
        "bra LW_%=;\n\t"
        "LD_%=:\n\t}"
        :: "r"(lbar), "r"(parity) : "memory");
}

// dot of 8 fp16 weights (uint4) with 8 fp32 x values (two float4), fp32 accum
__device__ __forceinline__ float dot8h(uint4 w, float4 xa, float4 xb) {
    __half2* hw = reinterpret_cast<__half2*>(&w);
    float2 f0 = __half22float2(hw[0]);
    float2 f1 = __half22float2(hw[1]);
    float2 f2 = __half22float2(hw[2]);
    float2 f3 = __half22float2(hw[3]);
    return f0.x * xa.x + f0.y * xa.y + f1.x * xa.z + f1.y * xa.w
         + f2.x * xb.x + f2.y * xb.y + f3.x * xb.z + f3.y * xb.w;
}

// ---------------------------------------------------------------------------
// Kernel B: 4-CTA cluster per batch element (32 clusters = 128 CTAs).
// Row-sliced W_a (rank owns rows [64r,64r+64), fp16 SMEM): z/yH are LOCAL
// GEMVs from the gathered full h (pushed pre-B0 with the score partials).
// 2 cluster barriers/step; gates-sum fused into the cell.
// ---------------------------------------------------------------------------
__global__ void __launch_bounds__(NTH, 1) __cluster_dims__(CL, 1, 1)
recur_kernel(
    const int*   __restrict__ lens,
    const float* __restrict__ W_a,    // [256, 512]
    const float* __restrict__ b_a,    // [256]
    float* __restrict__ out)          // output[T,B,H] ++ h_fin[B,H] ++ c_fin[B,H]
{
    extern __shared__ float smf[];
    unsigned long long* mbar = (unsigned long long*)smf;   // 2 barriers
    float* waZ_f   = smf     + SZ_MBAR;
    float* whhS_f  = waZ_f   + SZ_WAZ;
    float* zbuf    = whhS_f  + SZ_WHHS;
    float* buf     = zbuf    + SZ_ZBUF;
    float* scp     = buf     + SZ_BUF;
    float* alpha   = scp     + SZ_SCP;
    float* h_full  = alpha   + SZ_ALPHA;
    float* hu_full = h_full  + SZ_HFULL;
    float* y1part  = hu_full + SZ_HUFULL;
    float* yH_loc  = y1part  + SZ_Y1PART;
    float* xps     = yH_loc  + SZ_YHLOC;
    float* scstage = xps     + SZ_XPS;
    float* h_loc   = scstage + SZ_SCSTG;
    float* c_loc   = h_loc   + SZ_HLOC;
    float* ba_s    = c_loc   + SZ_CLOC;
    float* gpart   = ba_s    + SZ_BAS;     // SZ_GPART floats; ends at SMEM_FLOATS

    __half* waH  = (__half*)waZ_f;
    uint4*  waU  = (uint4*)waZ_f;
    uint4*  whhS = (uint4*)whhS_f;

    const int tid  = threadIdx.x;
    const int warp = tid >> 5, lane = tid & 31;
    const int r    = (int)my_rank();
    const int b    = blockIdx.x / CL;
    const int myLen = lens[b];

    const uint32_t bar0 = smem_u32(&mbar[0]);
    const uint32_t bar1 = smem_u32(&mbar[1]);

    // ---- one-time: W_a rows [64r,64r+64) -> fp16 SMEM [hs][k8][row][e] ----
    for (int idx = tid; idx < 32768; idx += NTH) {
        int e = idx & 7, row = (idx >> 3) & 63, k8 = (idx >> 9) & 31, hs = idx >> 14;
        int col = hs * 256 + k8 * 8 + e;
        waH[idx] = __float2half_rn(W_a[(size_t)(JS * r + row) * 512 + col]);
    }
    // ---- one-time: W_hh k-lo half -> SMEM (4096 uint4) ----
    {
        const uint4* src = (const uint4*)g_whh16 + (r * 2 + 0) * 4096;
        for (int i = tid; i < 4096; i += NTH) whhS[i] = __ldcg(&src[i]);
    }
    if (tid < JS) ba_s[tid] = __ldg(&b_a[JS * r + tid]);
    if (tid < 256) { hu_full[tid] = 0.f; h_full[tid] = 0.f; }
    if (tid < JS * 2) { h_loc[tid & 63] = 0.f; c_loc[tid & 63] = 0.f; }
    if (tid == 0) {
        #pragma unroll
        for (int k = 0; k < 2; k++)
            asm volatile("mbarrier.init.shared.b64 [%0], %1;"
                         :: "r"(smem_u32(&mbar[k])), "r"(CL) : "memory");
        asm volatile("fence.mbarrier_init.release.cluster;" ::: "memory");
    }
    __syncthreads();
    asm volatile("barrier.cluster.arrive.aligned;" ::: "memory");
    asm volatile("barrier.cluster.wait.aligned;" ::: "memory");

    // streamed W_hh k-hi half base: thread covers row = tid&255 when tid>=256
    const uint4* WpHi = (const uint4*)g_whh16 + (r * 2 + 1) * 4096 + (tid & 255);

    for (int t = 0; t < TT; t++) {
        const uint32_t par = (uint32_t)(t & 1);

        // ======== P1: local score partials; stage xproj ======================
        if (t > 0) {
            for (int blk = warp; blk * 4 < t; blk += 16) {
                int g = lane >> 3, L = lane & 7;
                int s = blk * 4 + g;
                float acc = 0.f;
                if (s < t) {
                    float4 b0 = *(const float4*)&buf[s * 64 + L * 8];
                    float4 b1 = *(const float4*)&buf[s * 64 + L * 8 + 4];
                    float4 h0 = *(const float4*)&h_loc[L * 8];
                    float4 h1 = *(const float4*)&h_loc[L * 8 + 4];
                    acc = b0.x * h0.x + b0.y * h0.y + b0.z * h0.z + b0.w * h0.w
                        + b1.x * h1.x + b1.y * h1.y + b1.z * h1.z + b1.w * h1.w;
                }
                acc += __shfl_xor_sync(0xffffffffu, acc, 1);
                acc += __shfl_xor_sync(0xffffffffu, acc, 2);
                acc += __shfl_xor_sync(0xffffffffu, acc, 4);
                if (L == 0 && s < t) scstage[s] = acc;
            }
        }
        if (tid < 256) {
            int grow = (tid >> 6) * 256 + JS * r + (tid & 63);
            xps[tid] = __ldg(&g_xproj[((size_t)t * BB + b) * G4 + grow]);
        }
        __syncthreads();

        // ---- pushes: full-h broadcast + score partials ----
        if (t > 0) {
            if (tid < 64) {               // h_loc -> h_full on all ranks
                int dest = tid >> 4, q = tid & 15;
                st_cluster4(smem_u32(&h_full[JS * r + q * 4]), dest,
                            *(const float4*)&h_loc[q * 4]);
            } else if (tid < 192) {       // score partials -> all ranks
                int i = tid - 64, chunk = i >> 2, peer = i & 3;
                if (chunk * 4 < t)
                    st_cluster4(smem_u32(&scp[r * 128 + chunk * 4]), peer,
                                *(const float4*)&scstage[chunk * 4]);
            }
        }
        if (tid < CL) bar_arrive_rank(bar0, tid);
        bar_wait(bar0, par);                                          // B0

        // ======== P2: [softmax warp0] || [local z/yH GEMV]; y1; hu; push ====
        if (t > 0) {
            {   // local GEMV: 512 thr = 64 rows x (2 hs x 4 chunks)
                int row = tid & 63, cg = tid >> 6;   // cg: hs=cg>>2, c=cg&3
                int hs = cg >> 2, c = cg & 3;
                const float4* h4 = (const float4*)h_full;
                float acc = 0.f;
                #pragma unroll
                for (int i = 0; i < 8; i++) {
                    int k8 = c * 8 + i;
                    acc += dot8h(waU[hs * 2048 + k8 * 64 + row],
                                 h4[k8 * 2], h4[k8 * 2 + 1]);
                }
                gpart[cg * 64 + row] = acc;
            }
            if (warp == 0) {  // softmax (replicated per rank)
                float v[4];
                float m = -1e30f;
                #pragma unroll
                for (int c = 0; c < 4; c++) {
                    int s = lane + 32 * c;
                    float sum = -1e30f;
                    if (s < t)
                        sum = scp[0 * 128 + s] + scp[1 * 128 + s]
                            + scp[2 * 128 + s] + scp[3 * 128 + s];
                    v[c] = sum;
                    m = fmaxf(m, sum);
                }
                #pragma unroll
                for (int o = 16; o > 0; o >>= 1) m = fmaxf(m, __shfl_xor_sync(0xffffffffu, m, o));
                float tot = 0.f;
                #pragma unroll
                for (int c = 0; c < 4; c++) {
                    int s = lane + 32 * c;
                    if (s < t) { v[c] = __expf(v[c] - m); tot += v[c]; }
                }
                #pragma unroll
                for (int o = 16; o > 0; o >>= 1) tot += __shfl_xor_sync(0xffffffffu, tot, o);
                float inv = 1.f / tot;
                #pragma unroll
                for (int c = 0; c < 4; c++) {
                    int s = lane + 32 * c;
                    if (s < t) alpha[s] = v[c] * inv;
                }
            }
            __syncthreads();

            // reduce GEMV partials (128 thr) + y1 over s<t-1 (all 512 thr)
            if (tid < 128) {
                int hs = tid >> 6, row = tid & 63;
                float v = gpart[(hs * 4 + 0) * 64 + row] + gpart[(hs * 4 + 1) * 64 + row]
                        + gpart[(hs * 4 + 2) * 64 + row] + gpart[(hs * 4 + 3) * 64 + row];
                if (hs == 0) zbuf[(t - 1) * 64 + row] = v;
                else         yH_loc[row] = v;
            }
            {   // y1 partials over old history only (no dependency on reduce)
                int g = tid >> 6, row = tid & 63;
                float acc = 0.f;
                for (int s = g; s < t - 1; s += 8) acc += alpha[s] * zbuf[s * 64 + row];
                y1part[g * 64 + row] = acc;
            }
            __syncthreads();

            if (tid < 16) {   // hu rows (4 per thread) + push float4 to all ranks
                float hv[4];
                float aT = alpha[t - 1];
                #pragma unroll
                for (int rr = 0; rr < 4; rr++) {
                    int row = tid * 4 + rr;
                    float y = y1part[0 * 64 + row] + y1part[1 * 64 + row]
                            + y1part[2 * 64 + row] + y1part[3 * 64 + row]
                            + y1part[4 * 64 + row] + y1part[5 * 64 + row]
                            + y1part[6 * 64 + row] + y1part[7 * 64 + row]
                            + yH_loc[row] + aT * zbuf[(t - 1) * 64 + row];
                    hv[rr] = tanhf(y + ba_s[row]);
                }
                float4 hv4 = make_float4(hv[0], hv[1], hv[2], hv[3]);
                #pragma unroll
                for (int dest = 0; dest < CL; dest++)
                    st_cluster4(smem_u32(&hu_full[JS * r + tid * 4]), dest, hv4);
            }
        }
        if (tid < CL) bar_arrive_rank(bar1, tid);
        bar_wait(bar1, par);                                          // B1

        // ======== P3: gates GEMV; k-lo from SMEM, k-hi streamed =============
        {
            int hs = tid >> 8, row = tid & 255;
            const float4* x4 = (const float4*)&hu_full[hs * 128];
            float acc = 0.f;
            if (hs == 0) {
                const uint4* W = whhS + row;
                #pragma unroll
                for (int i = 0; i < 16; i++)
                    acc += dot8h(W[i * 256], x4[i * 2], x4[i * 2 + 1]);
            } else {
                #pragma unroll
                for (int i = 0; i < 16; i++)
                    acc += dot8h(__ldcg(WpHi + i * 256), x4[i * 2], x4[i * 2 + 1]);
            }
            gpart[tid] = acc;
        }
        __syncthreads();

        // ======== fused gates-sum + cell update on my j-slice ===============
        if (tid < JS) {
            int j = JS * r + tid;
            float gv[4];
            #pragma unroll
            for (int g = 0; g < 4; g++) {
                int row = g * 64 + tid;
                gv[g] = gpart[row] + gpart[256 + row] + xps[row];
            }
            float si = 1.f / (1.f + __expf(-gv[0]));
            float sf = 1.f / (1.f + __expf(-gv[1]));
            float so = 1.f / (1.f + __expf(-gv[3]));
            float cn = sf * c_loc[tid] + si * tanhf(gv[2]);
            float hn = so * tanhf(cn);
            c_loc[tid] = cn;
            h_loc[tid] = hn;
            buf[t * 64 + tid] = hn;

            out[((size_t)t * BB + b) * HH + j] = hn;
            if (t == myLen - 1) {
                out[(size_t)TT * BB * HH + (size_t)b * HH + j] = hn;
                out[(size_t)TT * BB * HH + (size_t)BB * HH + (size_t)b * HH + j] = cn;
            }
        }
        __syncthreads();
    }
}

// ---------------------------------------------------------------------------
extern "C" void kernel_launch(void* const* d_in, const int* in_sizes, int n_in,
                              void* d_out, int out_size)
{
    const float* embs = (const float*)d_in[0];
    const int*   lens = (const int*)  d_in[1];
    const float* W_ih = (const float*)d_in[2];
    const float* W_hh = (const float*)d_in[3];
    const float* b_ih = (const float*)d_in[4];
    const float* b_hh = (const float*)d_in[5];
    const float* W_a  = (const float*)d_in[6];
    const float* b_a  = (const float*)d_in[7];
    float* out = (float*)d_out;

    const int smem_bytes = SMEM_FLOATS * (int)sizeof(float);   // 51976*4 = 207,904 B
    cudaFuncSetAttribute(recur_kernel, cudaFuncAttributeMaxDynamicSharedMemorySize, smem_bytes);

    whh16_kernel<<<1024, 256>>>(W_hh);
    xproj_kernel<<<dim3((TT * BB) / 64, G4 / 64), 256>>>(embs, W_ih, b_ih, b_hh);
    recur_kernel<<<BB * CL, NTH, smem_bytes>>>(lens, W_a, b_a, out);
}

// round 13
// speedup vs baseline: 7.4079x; 1.0314x over previous
#include <cuda_runtime.h>
#include <cuda_fp16.h>
#include <cstdint>
#include <math.h>

#define TT 128
#define BB 32
#define HH 256
#define II 256
#define G4 1024   // 4*H
#define CL 4      // CTAs per cluster
#define NTH 512
#define JS 64     // j-slice per rank (HH/CL)

// ---- SMEM layout sizes (floats) — single source of truth ------------------
#define SZ_MBAR    8
#define SZ_WAZ     16384   // W_a slice, fp16 (32768 halves = 64 KB)
#define SZ_WHHS    24576   // W_hh resident: 6144 uint4 = 96 KB (k0-127 all rows + k128-191)
#define SZ_ZBUF    4096    // z history fp16: 128 x 64 halves
#define SZ_BUF     4096    // h history fp16: 128 x 64 halves
#define SZ_SCP     512
#define SZ_ALPHA   128
#define SZ_HFULL   256
#define SZ_HUFULL  256
#define SZ_Y1PART  512
#define SZ_YHLOC   64
#define SZ_XPS     256
#define SZ_SCSTG   128
#define SZ_HLOC    64
#define SZ_CLOC    64
#define SZ_BAS     64
#define SZ_GPART   512
#define SMEM_FLOATS (SZ_MBAR + SZ_WAZ + SZ_WHHS + SZ_ZBUF + SZ_BUF + SZ_SCP \
                   + SZ_ALPHA + SZ_HFULL + SZ_HUFULL + SZ_Y1PART + SZ_YHLOC \
                   + SZ_XPS + SZ_SCSTG + SZ_HLOC + SZ_CLOC + SZ_BAS + SZ_GPART)
// = 51976 floats = 207,904 B

// Scratch: hoisted input projection xproj[t][b][row]
__device__ float g_xproj[(size_t)TT * BB * G4];       // 16 MB
// fp16 W_hh, permuted per rank into two k-halves (see whh16_kernel)
__device__ __half g_whh16[CL * 2 * 16 * 256 * 8];     // 512 KB

// ---------------------------------------------------------------------------
// Kernel A: xproj = emb @ W_ih^T + (b_ih + b_hh)   (M=4096, N=1024, K=256)
// ---------------------------------------------------------------------------
__global__ void __launch_bounds__(256) xproj_kernel(
    const float* __restrict__ emb, const float* __restrict__ W_ih,
    const float* __restrict__ b_ih, const float* __restrict__ b_hh)
{
    __shared__ float As[64][65];
    __shared__ float Bs[64][65];
    const int K = II;
    const int bm = blockIdx.x * 64, bn = blockIdx.y * 64;
    const int tx = threadIdx.x & 15, ty = threadIdx.x >> 4;
    float acc[4][4] = {};

    for (int k0 = 0; k0 < K; k0 += 64) {
        for (int i = threadIdx.x; i < 64 * 64; i += 256) {
            int r = i >> 6, cc = i & 63;
            As[r][cc] = emb[(size_t)(bm + r) * K + k0 + cc];
            Bs[r][cc] = W_ih[(size_t)(bn + r) * K + k0 + cc];
        }
        __syncthreads();
        #pragma unroll
        for (int k = 0; k < 64; k++) {
            float a[4], bv[4];
            #pragma unroll
            for (int i = 0; i < 4; i++) a[i] = As[ty * 4 + i][k];
            #pragma unroll
            for (int j = 0; j < 4; j++) bv[j] = Bs[tx * 4 + j][k];
            #pragma unroll
            for (int i = 0; i < 4; i++)
                #pragma unroll
                for (int j = 0; j < 4; j++)
                    acc[i][j] += a[i] * bv[j];
        }
        __syncthreads();
    }
    #pragma unroll
    for (int i = 0; i < 4; i++)
        #pragma unroll
        for (int j = 0; j < 4; j++) {
            int r = bm + ty * 4 + i, cI = bn + tx * 4 + j;
            g_xproj[(size_t)r * G4 + cI] = acc[i][j] + b_ih[cI] + b_hh[cI];
        }
}

// ---------------------------------------------------------------------------
// Kernel A2: convert + permute W_hh into g_whh16 (two k-halves per rank)
// ---------------------------------------------------------------------------
__global__ void __launch_bounds__(256) whh16_kernel(const float* __restrict__ W_hh)
{
    int idx = blockIdx.x * 256 + threadIdx.x;        // 262144 total halves
    int e    = idx & 7;
    int row  = (idx >> 3) & 255;
    int i    = (idx >> 11) & 15;
    int part = (idx >> 15) & 1;
    int rr   = idx >> 16;
    int grow = (row >> 6) * 256 + 64 * rr + (row & 63);
    int k    = part * 128 + i * 8 + e;
    g_whh16[idx] = __float2half_rn(W_hh[(size_t)grow * HH + k]);
}

// ---------------------------------------------------------------------------
// DSMEM / mbarrier helpers (vectorized stores, no atomics)
// ---------------------------------------------------------------------------
__device__ __forceinline__ uint32_t smem_u32(const void* p) {
    return (uint32_t)__cvta_generic_to_shared(p);
}
__device__ __forceinline__ uint32_t my_rank() {
    uint32_t r;
    asm("mov.u32 %0, %%cluster_ctarank;" : "=r"(r));
    return r;
}
__device__ __forceinline__ void st_cluster4(uint32_t laddr, int rank, float4 v) {
    uint32_t ra;
    asm volatile("mapa.shared::cluster.u32 %0, %1, %2;" : "=r"(ra) : "r"(laddr), "r"(rank));
    asm volatile("st.shared::cluster.v4.f32 [%0], {%1,%2,%3,%4};"
                 :: "r"(ra), "f"(v.x), "f"(v.y), "f"(v.z), "f"(v.w) : "memory");
}
__device__ __forceinline__ void bar_arrive_rank(uint32_t lbar, int rank) {
    uint32_t ra;
    asm volatile("mapa.shared::cluster.u32 %0, %1, %2;" : "=r"(ra) : "r"(lbar), "r"(rank));
    asm volatile("mbarrier.arrive.release.cluster.shared::cluster.b64 _, [%0];"
                 :: "r"(ra) : "memory");
}
__device__ __forceinline__ void bar_wait(uint32_t lbar, uint32_t parity) {
    asm volatile(
        "{\n\t.reg .pred P;\n\t"
        "LW_%=:\n\t"
        "mbarrier.try_wait.parity.acquire.cluster.shared::cta.b64 P, [%0], %1, 0x989680;\n\t"
        "@P bra LD_%=;\n\t"
        "bra LW_%=;\n\t"
        "LD_%=:\n\t}"
        :: "r"(lbar), "r"(parity) : "memory");
}

// dot of 8 fp16 values (uint4) with 8 fp32 x values (two float4), fp32 accum
__device__ __forceinline__ float dot8h(uint4 w, float4 xa, float4 xb) {
    __half2* hw = reinterpret_cast<__half2*>(&w);
    float2 f0 = __half22float2(hw[0]);
    float2 f1 = __half22float2(hw[1]);
    float2 f2 = __half22float2(hw[2]);
    float2 f3 = __half22float2(hw[3]);
    return f0.x * xa.x + f0.y * xa.y + f1.x * xa.z + f1.y * xa.w
         + f2.x * xb.x + f2.y * xb.y + f3.x * xb.z + f3.y * xb.w;
}

// fast tanh via MUFU exp: (e^{2x}-1)/(e^{2x}+1), clamped to avoid inf/inf
__device__ __forceinline__ float tanh_fast(float x) {
    x = fminf(fmaxf(x, -15.f), 15.f);
    float e = __expf(2.f * x);
    return __fdividef(e - 1.f, e + 1.f);
}

// ---------------------------------------------------------------------------
// Kernel B: 4-CTA cluster per batch element (32 clusters = 128 CTAs).
// Row-sliced W_a (fp16 SMEM); fp16 h/z history; W_hh 96KB resident +
// 32KB streamed. 2 cluster barriers/step; gates-sum fused into the cell.
// ---------------------------------------------------------------------------
__global__ void __launch_bounds__(NTH, 1) __cluster_dims__(CL, 1, 1)
recur_kernel(
    const int*   __restrict__ lens,
    const float* __restrict__ W_a,    // [256, 512]
    const float* __restrict__ b_a,    // [256]
    float* __restrict__ out)          // output[T,B,H] ++ h_fin[B,H] ++ c_fin[B,H]
{
    extern __shared__ float smf[];
    unsigned long long* mbar = (unsigned long long*)smf;   // 2 barriers
    float* waZ_f   = smf     + SZ_MBAR;
    float* whhS_f  = waZ_f   + SZ_WAZ;
    float* zbuf_f  = whhS_f  + SZ_WHHS;
    float* buf_f   = zbuf_f  + SZ_ZBUF;
    float* scp     = buf_f   + SZ_BUF;
    float* alpha   = scp     + SZ_SCP;
    float* h_full  = alpha   + SZ_ALPHA;
    float* hu_full = h_full  + SZ_HFULL;
    float* y1part  = hu_full + SZ_HUFULL;
    float* yH_loc  = y1part  + SZ_Y1PART;
    float* xps     = yH_loc  + SZ_YHLOC;
    float* scstage = xps     + SZ_XPS;
    float* h_loc   = scstage + SZ_SCSTG;
    float* c_loc   = h_loc   + SZ_HLOC;
    float* ba_s    = c_loc   + SZ_CLOC;
    float* gpart   = ba_s    + SZ_BAS;     // SZ_GPART floats; ends at SMEM_FLOATS

    __half* waH    = (__half*)waZ_f;
    uint4*  waU    = (uint4*)waZ_f;
    uint4*  whhS   = (uint4*)whhS_f;       // [0..4095]: k0-127; [4096..6143]: k128-191
    __half* zbuf_h = (__half*)zbuf_f;
    __half* buf_h  = (__half*)buf_f;
    uint4*  buf_u4 = (uint4*)buf_f;        // buf_u4[s*8 + L] = halves k=L*8..L*8+7

    const int tid  = threadIdx.x;
    const int warp = tid >> 5, lane = tid & 31;
    const int r    = (int)my_rank();
    const int b    = blockIdx.x / CL;
    const int myLen = lens[b];

    const uint32_t bar0 = smem_u32(&mbar[0]);
    const uint32_t bar1 = smem_u32(&mbar[1]);

    // ---- one-time: W_a rows [64r,64r+64) -> fp16 SMEM [hs][k8][row][e] ----
    for (int idx = tid; idx < 32768; idx += NTH) {
        int e = idx & 7, row = (idx >> 3) & 63, k8 = (idx >> 9) & 31, hs = idx >> 14;
        int col = hs * 256 + k8 * 8 + e;
        waH[idx] = __float2half_rn(W_a[(size_t)(JS * r + row) * 512 + col]);
    }
    // ---- one-time: W_hh resident parts -> SMEM (6144 uint4 = 96 KB) ----
    {
        const uint4* src0 = (const uint4*)g_whh16 + (r * 2 + 0) * 4096;
        const uint4* src1 = (const uint4*)g_whh16 + (r * 2 + 1) * 4096;
        for (int i = tid; i < 4096; i += NTH) whhS[i] = __ldcg(&src0[i]);
        for (int i = tid; i < 2048; i += NTH) whhS[4096 + i] = __ldcg(&src1[i]);
    }
    if (tid < JS) ba_s[tid] = __ldg(&b_a[JS * r + tid]);
    if (tid < 256) { hu_full[tid] = 0.f; h_full[tid] = 0.f; }
    if (tid < JS * 2) { h_loc[tid & 63] = 0.f; c_loc[tid & 63] = 0.f; }
    if (tid == 0) {
        #pragma unroll
        for (int k = 0; k < 2; k++)
            asm volatile("mbarrier.init.shared.b64 [%0], %1;"
                         :: "r"(smem_u32(&mbar[k])), "r"(CL) : "memory");
        asm volatile("fence.mbarrier_init.release.cluster;" ::: "memory");
    }
    __syncthreads();
    asm volatile("barrier.cluster.arrive.aligned;" ::: "memory");
    asm volatile("barrier.cluster.wait.aligned;" ::: "memory");

    // streamed W_hh k[192:256) base (part1, i=8..15): row = tid&255
    const uint4* WpHi = (const uint4*)g_whh16 + (r * 2 + 1) * 4096 + (tid & 255);

    for (int t = 0; t < TT; t++) {
        const uint32_t par = (uint32_t)(t & 1);

        // ======== P1: local score partials (fp16 history); stage xproj ======
        if (t > 0) {
            const float4* h4l = (const float4*)h_loc;
            for (int blk = warp; blk * 4 < t; blk += 16) {
                int g = lane >> 3, L = lane & 7;
                int s = blk * 4 + g;
                float acc = 0.f;
                if (s < t) {
                    uint4 hw = buf_u4[s * 8 + L];
                    acc = dot8h(hw, h4l[L * 2], h4l[L * 2 + 1]);
                }
                acc += __shfl_xor_sync(0xffffffffu, acc, 1);
                acc += __shfl_xor_sync(0xffffffffu, acc, 2);
                acc += __shfl_xor_sync(0xffffffffu, acc, 4);
                if (L == 0 && s < t) scstage[s] = acc;
            }
        }
        if (tid < 256) {
            int grow = (tid >> 6) * 256 + JS * r + (tid & 63);
            xps[tid] = __ldg(&g_xproj[((size_t)t * BB + b) * G4 + grow]);
        }
        __syncthreads();

        // ---- pushes: full-h broadcast + score partials ----
        if (t > 0) {
            if (tid < 64) {               // h_loc -> h_full on all ranks
                int dest = tid >> 4, q = tid & 15;
                st_cluster4(smem_u32(&h_full[JS * r + q * 4]), dest,
                            *(const float4*)&h_loc[q * 4]);
            } else if (tid < 192) {       // score partials -> all ranks
                int i = tid - 64, chunk = i >> 2, peer = i & 3;
                if (chunk * 4 < t)
                    st_cluster4(smem_u32(&scp[r * 128 + chunk * 4]), peer,
                                *(const float4*)&scstage[chunk * 4]);
            }
        }
        if (tid < CL) bar_arrive_rank(bar0, tid);
        bar_wait(bar0, par);                                          // B0

        // ======== P2: [softmax warp0] || [local z/yH GEMV]; y1; hu; push ====
        if (t > 0) {
            {   // local GEMV: 512 thr = 64 rows x (2 hs x 4 chunks)
                int row = tid & 63, cg = tid >> 6;   // cg: hs=cg>>2, c=cg&3
                int hs = cg >> 2, c = cg & 3;
                const float4* h4 = (const float4*)h_full;
                float acc = 0.f;
                #pragma unroll
                for (int i = 0; i < 8; i++) {
                    int k8 = c * 8 + i;
                    acc += dot8h(waU[hs * 2048 + k8 * 64 + row],
                                 h4[k8 * 2], h4[k8 * 2 + 1]);
                }
                gpart[cg * 64 + row] = acc;
            }
            if (warp == 0) {  // softmax (replicated per rank)
                float v[4];
                float m = -1e30f;
                #pragma unroll
                for (int c = 0; c < 4; c++) {
                    int s = lane + 32 * c;
                    float sum = -1e30f;
                    if (s < t)
                        sum = scp[0 * 128 + s] + scp[1 * 128 + s]
                            + scp[2 * 128 + s] + scp[3 * 128 + s];
                    v[c] = sum;
                    m = fmaxf(m, sum);
                }
                #pragma unroll
                for (int o = 16; o > 0; o >>= 1) m = fmaxf(m, __shfl_xor_sync(0xffffffffu, m, o));
                float tot = 0.f;
                #pragma unroll
                for (int c = 0; c < 4; c++) {
                    int s = lane + 32 * c;
                    if (s < t) { v[c] = __expf(v[c] - m); tot += v[c]; }
                }
                #pragma unroll
                for (int o = 16; o > 0; o >>= 1) tot += __shfl_xor_sync(0xffffffffu, tot, o);
                float inv = 1.f / tot;
                #pragma unroll
                for (int c = 0; c < 4; c++) {
                    int s = lane + 32 * c;
                    if (s < t) alpha[s] = v[c] * inv;
                }
            }
            __syncthreads();

            // reduce GEMV partials (128 thr) + y1 over s<t-1 (all 512 thr)
            if (tid < 128) {
                int hs = tid >> 6, row = tid & 63;
                float v = gpart[(hs * 4 + 0) * 64 + row] + gpart[(hs * 4 + 1) * 64 + row]
                        + gpart[(hs * 4 + 2) * 64 + row] + gpart[(hs * 4 + 3) * 64 + row];
                if (hs == 0) zbuf_h[(t - 1) * 64 + row] = __float2half_rn(v);
                else         yH_loc[row] = v;
            }
            {   // y1 partials over old history only
                int g = tid >> 6, row = tid & 63;
                float acc = 0.f;
                for (int s = g; s < t - 1; s += 8)
                    acc += alpha[s] * __half2float(zbuf_h[s * 64 + row]);
                y1part[g * 64 + row] = acc;
            }
            __syncthreads();

            if (tid < 16) {   // hu rows (4 per thread) + push float4 to all ranks
                float hv[4];
                float aT = alpha[t - 1];
                #pragma unroll
                for (int rr = 0; rr < 4; rr++) {
                    int row = tid * 4 + rr;
                    float y = y1part[0 * 64 + row] + y1part[1 * 64 + row]
                            + y1part[2 * 64 + row] + y1part[3 * 64 + row]
                            + y1part[4 * 64 + row] + y1part[5 * 64 + row]
                            + y1part[6 * 64 + row] + y1part[7 * 64 + row]
                            + yH_loc[row]
                            + aT * __half2float(zbuf_h[(t - 1) * 64 + row]);
                    hv[rr] = tanh_fast(y + ba_s[row]);
                }
                float4 hv4 = make_float4(hv[0], hv[1], hv[2], hv[3]);
                #pragma unroll
                for (int dest = 0; dest < CL; dest++)
                    st_cluster4(smem_u32(&hu_full[JS * r + tid * 4]), dest, hv4);
            }
        }
        if (tid < CL) bar_arrive_rank(bar1, tid);
        bar_wait(bar1, par);                                          // B1

        // ======== P3: gates GEMV; 96KB resident, 32KB streamed ==============
        {
            int hs = tid >> 8, row = tid & 255;
            const float4* x4 = (const float4*)&hu_full[hs * 128];
            float acc = 0.f;
            if (hs == 0) {
                const uint4* W = whhS + row;          // k[0:128)
                #pragma unroll
                for (int i = 0; i < 16; i++)
                    acc += dot8h(W[i * 256], x4[i * 2], x4[i * 2 + 1]);
            } else {
                const uint4* W = whhS + 4096 + row;   // k[128:192) resident
                #pragma unroll
                for (int i = 0; i < 8; i++)
                    acc += dot8h(W[i * 256], x4[i * 2], x4[i * 2 + 1]);
                #pragma unroll
                for (int i = 8; i < 16; i++)          // k[192:256) streamed
                    acc += dot8h(__ldcg(WpHi + i * 256), x4[i * 2], x4[i * 2 + 1]);
            }
            gpart[tid] = acc;
        }
        __syncthreads();

        // ======== fused gates-sum + cell update on my j-slice ===============
        if (tid < JS) {
            int j = JS * r + tid;
            float gv[4];
            #pragma unroll
            for (int g = 0; g < 4; g++) {
                int row = g * 64 + tid;
                gv[g] = gpart[row] + gpart[256 + row] + xps[row];
            }
            float si = 1.f / (1.f + __expf(-gv[0]));
            float sf = 1.f / (1.f + __expf(-gv[1]));
            float so = 1.f / (1.f + __expf(-gv[3]));
            float cn = sf * c_loc[tid] + si * tanh_fast(gv[2]);
            float hn = so * tanh_fast(cn);
            c_loc[tid] = cn;
            h_loc[tid] = hn;
            buf_h[t * 64 + tid] = __float2half_rn(hn);

            out[((size_t)t * BB + b) * HH + j] = hn;
            if (t == myLen - 1) {
                out[(size_t)TT * BB * HH + (size_t)b * HH + j] = hn;
                out[(size_t)TT * BB * HH + (size_t)BB * HH + (size_t)b * HH + j] = cn;
            }
        }
        __syncthreads();
    }
}

// ---------------------------------------------------------------------------
extern "C" void kernel_launch(void* const* d_in, const int* in_sizes, int n_in,
                              void* d_out, int out_size)
{
    const float* embs = (const float*)d_in[0];
    const int*   lens = (const int*)  d_in[1];
    const float* W_ih = (const float*)d_in[2];
    const float* W_hh = (const float*)d_in[3];
    const float* b_ih = (const float*)d_in[4];
    const float* b_hh = (const float*)d_in[5];
    const float* W_a  = (const float*)d_in[6];
    const float* b_a  = (const float*)d_in[7];
    float* out = (float*)d_out;

    const int smem_bytes = SMEM_FLOATS * (int)sizeof(float);   // 207,904 B
    cudaFuncSetAttribute(recur_kernel, cudaFuncAttributeMaxDynamicSharedMemorySize, smem_bytes);

    whh16_kernel<<<1024, 256>>>(W_hh);
    xproj_kernel<<<dim3((TT * BB) / 64, G4 / 64), 256>>>(embs, W_ih, b_ih, b_hh);
    recur_kernel<<<BB * CL, NTH, smem_bytes>>>(lens, W_a, b_a, out);
}

// round 14
// speedup vs baseline: 8.0801x; 1.0907x over previous
#include <cuda_runtime.h>
#include <cuda_fp16.h>
#include <cstdint>
#include <math.h>

#define TT 128
#define BB 32
#define HH 256
#define II 256
#define G4 1024   // 4*H
#define CL 4      // CTAs per cluster
#define NTH 512
#define JS 64     // j-slice per rank (HH/CL)

// ---- SMEM layout sizes (floats) — single source of truth ------------------
#define SZ_MBAR    8
#define SZ_WAZ     16384   // W_a slice fp16 (32768 halves = 64 KB)
#define SZ_WHHS    28672   // W_hh resident fp16: 7168 uint4 = 112 KB
#define SZ_ZBUF    4096    // z history fp16: 128 x 64 halves
#define SZ_BUF     4096    // h history fp16: 128 x 64 halves
#define SZ_SCP     512
#define SZ_ALPHA   128
#define SZ_HFULLH  128     // h_full fp16: 256 halves
#define SZ_HUFULLH 128     // hu_full fp16: 256 halves
#define SZ_Y1PART  512
#define SZ_YHLOC   64
#define SZ_XPS     256
#define SZ_SCSTG   128
#define SZ_HLOCH   32      // h_loc fp16: 64 halves
#define SZ_CLOC    64
#define SZ_BAS     64
#define SZ_GPART   512
#define SMEM_FLOATS (SZ_MBAR + SZ_WAZ + SZ_WHHS + SZ_ZBUF + SZ_BUF + SZ_SCP \
                   + SZ_ALPHA + SZ_HFULLH + SZ_HUFULLH + SZ_Y1PART + SZ_YHLOC \
                   + SZ_XPS + SZ_SCSTG + SZ_HLOCH + SZ_CLOC + SZ_BAS + SZ_GPART)
// = 55784 floats = 223,136 B  (< 227 KB cap)

// Scratch: hoisted input projection xproj[t][b][row]
__device__ float g_xproj[(size_t)TT * BB * G4];       // 16 MB
// fp16 W_hh, permuted per rank into two k-halves (see whh16_kernel)
__device__ __half g_whh16[CL * 2 * 16 * 256 * 8];     // 512 KB

// ---------------------------------------------------------------------------
// Kernel A: xproj = emb @ W_ih^T + (b_ih + b_hh)   (M=4096, N=1024, K=256)
// ---------------------------------------------------------------------------
__global__ void __launch_bounds__(256) xproj_kernel(
    const float* __restrict__ emb, const float* __restrict__ W_ih,
    const float* __restrict__ b_ih, const float* __restrict__ b_hh)
{
    __shared__ float As[64][65];
    __shared__ float Bs[64][65];
    const int K = II;
    const int bm = blockIdx.x * 64, bn = blockIdx.y * 64;
    const int tx = threadIdx.x & 15, ty = threadIdx.x >> 4;
    float acc[4][4] = {};

    for (int k0 = 0; k0 < K; k0 += 64) {
        for (int i = threadIdx.x; i < 64 * 64; i += 256) {
            int r = i >> 6, cc = i & 63;
            As[r][cc] = emb[(size_t)(bm + r) * K + k0 + cc];
            Bs[r][cc] = W_ih[(size_t)(bn + r) * K + k0 + cc];
        }
        __syncthreads();
        #pragma unroll
        for (int k = 0; k < 64; k++) {
            float a[4], bv[4];
            #pragma unroll
            for (int i = 0; i < 4; i++) a[i] = As[ty * 4 + i][k];
            #pragma unroll
            for (int j = 0; j < 4; j++) bv[j] = Bs[tx * 4 + j][k];
            #pragma unroll
            for (int i = 0; i < 4; i++)
                #pragma unroll
                for (int j = 0; j < 4; j++)
                    acc[i][j] += a[i] * bv[j];
        }
        __syncthreads();
    }
    #pragma unroll
    for (int i = 0; i < 4; i++)
        #pragma unroll
        for (int j = 0; j < 4; j++) {
            int r = bm + ty * 4 + i, cI = bn + tx * 4 + j;
            g_xproj[(size_t)r * G4 + cI] = acc[i][j] + b_ih[cI] + b_hh[cI];
        }
}

// ---------------------------------------------------------------------------
// Kernel A2: convert + permute W_hh into g_whh16 (two k-halves per rank)
// ---------------------------------------------------------------------------
__global__ void __launch_bounds__(256) whh16_kernel(const float* __restrict__ W_hh)
{
    int idx = blockIdx.x * 256 + threadIdx.x;        // 262144 total halves
    int e    = idx & 7;
    int row  = (idx >> 3) & 255;
    int i    = (idx >> 11) & 15;
    int part = (idx >> 15) & 1;
    int rr   = idx >> 16;
    int grow = (row >> 6) * 256 + 64 * rr + (row & 63);
    int k    = part * 128 + i * 8 + e;
    g_whh16[idx] = __float2half_rn(W_hh[(size_t)grow * HH + k]);
}

// ---------------------------------------------------------------------------
// DSMEM / mbarrier helpers (vectorized stores, no atomics)
// ---------------------------------------------------------------------------
__device__ __forceinline__ uint32_t smem_u32(const void* p) {
    return (uint32_t)__cvta_generic_to_shared(p);
}
__device__ __forceinline__ uint32_t my_rank() {
    uint32_t r;
    asm("mov.u32 %0, %%cluster_ctarank;" : "=r"(r));
    return r;
}
__device__ __forceinline__ void st_cluster4(uint32_t laddr, int rank, float4 v) {
    uint32_t ra;
    asm volatile("mapa.shared::cluster.u32 %0, %1, %2;" : "=r"(ra) : "r"(laddr), "r"(rank));
    asm volatile("st.shared::cluster.v4.f32 [%0], {%1,%2,%3,%4};"
                 :: "r"(ra), "f"(v.x), "f"(v.y), "f"(v.z), "f"(v.w) : "memory");
}
__device__ __forceinline__ void st_cluster2(uint32_t laddr, int rank, uint2 v) {
    uint32_t ra;
    asm volatile("mapa.shared::cluster.u32 %0, %1, %2;" : "=r"(ra) : "r"(laddr), "r"(rank));
    asm volatile("st.shared::cluster.v2.b32 [%0], {%1,%2};"
                 :: "r"(ra), "r"(v.x), "r"(v.y) : "memory");
}
__device__ __forceinline__ void bar_arrive_rank(uint32_t lbar, int rank) {
    uint32_t ra;
    asm volatile("mapa.shared::cluster.u32 %0, %1, %2;" : "=r"(ra) : "r"(lbar), "r"(rank));
    asm volatile("mbarrier.arrive.release.cluster.shared::cluster.b64 _, [%0];"
                 :: "r"(ra) : "memory");
}
__device__ __forceinline__ void bar_wait(uint32_t lbar, uint32_t parity) {
    asm volatile(
        "{\n\t.reg .pred P;\n\t"
        "LW_%=:\n\t"
        "mbarrier.try_wait.parity.acquire.cluster.shared::cta.b64 P, [%0], %1, 0x989680;\n\t"
        "@P bra LD_%=;\n\t"
        "bra LW_%=;\n\t"
        "LD_%=:\n\t}"
        :: "r"(lbar), "r"(parity) : "memory");
}

// dot of 8 fp16 x 8 fp16 (uint4 each), half2 accumulate, fp32 result
__device__ __forceinline__ float dot8hh(uint4 w, uint4 x) {
    const __half2* hw = reinterpret_cast<const __half2*>(&w);
    const __half2* hx = reinterpret_cast<const __half2*>(&x);
    __half2 a = __hmul2(hw[0], hx[0]);
    a = __hfma2(hw[1], hx[1], a);
    a = __hfma2(hw[2], hx[2], a);
    a = __hfma2(hw[3], hx[3], a);
    float2 f = __half22float2(a);
    return f.x + f.y;
}

// fast tanh via MUFU exp: (e^{2x}-1)/(e^{2x}+1), clamped to avoid inf/inf
__device__ __forceinline__ float tanh_fast(float x) {
    x = fminf(fmaxf(x, -15.f), 15.f);
    float e = __expf(2.f * x);
    return __fdividef(e - 1.f, e + 1.f);
}

// ---------------------------------------------------------------------------
// Kernel B: 4-CTA cluster per batch element (32 clusters = 128 CTAs).
// fp16 everywhere in the GEMVs (HFMA2 inner product); W_hh 112 KB resident +
// 16 KB streamed. 2 cluster barriers/step (single-warp wait + syncthreads).
// ---------------------------------------------------------------------------
__global__ void __launch_bounds__(NTH, 1) __cluster_dims__(CL, 1, 1)
recur_kernel(
    const int*   __restrict__ lens,
    const float* __restrict__ W_a,    // [256, 512]
    const float* __restrict__ b_a,    // [256]
    float* __restrict__ out)          // output[T,B,H] ++ h_fin[B,H] ++ c_fin[B,H]
{
    extern __shared__ float smf[];
    unsigned long long* mbar = (unsigned long long*)smf;   // 2 barriers
    float* waZ_f   = smf      + SZ_MBAR;
    float* whhS_f  = waZ_f    + SZ_WAZ;
    float* zbuf_f  = whhS_f   + SZ_WHHS;
    float* buf_f   = zbuf_f   + SZ_ZBUF;
    float* scp     = buf_f    + SZ_BUF;
    float* alpha   = scp      + SZ_SCP;
    float* hfull_f = alpha    + SZ_ALPHA;
    float* hufull_f= hfull_f  + SZ_HFULLH;
    float* y1part  = hufull_f + SZ_HUFULLH;
    float* yH_loc  = y1part   + SZ_Y1PART;
    float* xps     = yH_loc   + SZ_YHLOC;
    float* scstage = xps      + SZ_XPS;
    float* hloc_f  = scstage  + SZ_SCSTG;
    float* c_loc   = hloc_f   + SZ_HLOCH;
    float* ba_s    = c_loc    + SZ_CLOC;
    float* gpart   = ba_s     + SZ_BAS;   // SZ_GPART floats; ends at SMEM_FLOATS

    __half* waH      = (__half*)waZ_f;
    uint4*  waU      = (uint4*)waZ_f;
    uint4*  whhS     = (uint4*)whhS_f;     // [0..4095]: k0-127; [4096..7167]: k128-223
    __half* zbuf_h   = (__half*)zbuf_f;
    __half* buf_h    = (__half*)buf_f;
    uint4*  buf_u4   = (uint4*)buf_f;      // buf_u4[s*8 + L] = halves k=L*8..L*8+7
    __half* hfull_h  = (__half*)hfull_f;
    uint4*  hfull_u4 = (uint4*)hfull_f;    // 32 uint4
    __half* hufull_h = (__half*)hufull_f;
    uint4*  hufull_u4= (uint4*)hufull_f;   // 32 uint4
    __half* hloc_h   = (__half*)hloc_f;    // 64 halves
    uint4*  hloc_u4  = (uint4*)hloc_f;     // 8 uint4

    const int tid  = threadIdx.x;
    const int warp = tid >> 5, lane = tid & 31;
    const int r    = (int)my_rank();
    const int b    = blockIdx.x / CL;
    const int myLen = lens[b];

    const uint32_t bar0 = smem_u32(&mbar[0]);
    const uint32_t bar1 = smem_u32(&mbar[1]);

    // ---- one-time: W_a rows [64r,64r+64) -> fp16 SMEM [hs][k8][row][e] ----
    for (int idx = tid; idx < 32768; idx += NTH) {
        int e = idx & 7, row = (idx >> 3) & 63, k8 = (idx >> 9) & 31, hs = idx >> 14;
        int col = hs * 256 + k8 * 8 + e;
        waH[idx] = __float2half_rn(W_a[(size_t)(JS * r + row) * 512 + col]);
    }
    // ---- one-time: W_hh resident parts -> SMEM (7168 uint4 = 112 KB) ----
    {
        const uint4* src0 = (const uint4*)g_whh16 + (r * 2 + 0) * 4096;
        const uint4* src1 = (const uint4*)g_whh16 + (r * 2 + 1) * 4096;
        for (int i = tid; i < 4096; i += NTH) whhS[i] = __ldcg(&src0[i]);
        for (int i = tid; i < 3072; i += NTH) whhS[4096 + i] = __ldcg(&src1[i]);
    }
    if (tid < JS) ba_s[tid] = __ldg(&b_a[JS * r + tid]);
    if (tid < 256) { hufull_h[tid] = __half(0.f); hfull_h[tid] = __half(0.f); }
    if (tid < 64) { hloc_h[tid] = __half(0.f); c_loc[tid] = 0.f; }
    if (tid == 0) {
        #pragma unroll
        for (int k = 0; k < 2; k++)
            asm volatile("mbarrier.init.shared.b64 [%0], %1;"
                         :: "r"(smem_u32(&mbar[k])), "r"(CL) : "memory");
        asm volatile("fence.mbarrier_init.release.cluster;" ::: "memory");
    }
    __syncthreads();
    asm volatile("barrier.cluster.arrive.aligned;" ::: "memory");
    asm volatile("barrier.cluster.wait.aligned;" ::: "memory");

    // streamed W_hh k[224:256) (part1, i=12..15): row = tid&255
    const uint4* WpHi = (const uint4*)g_whh16 + (r * 2 + 1) * 4096 + (tid & 255);

    for (int t = 0; t < TT; t++) {
        const uint32_t par = (uint32_t)(t & 1);

        // ======== P1: local score partials (all-fp16); stage xproj ==========
        if (t > 0) {
            for (int blk = warp; blk * 4 < t; blk += 16) {
                int g = lane >> 3, L = lane & 7;
                int s = blk * 4 + g;
                float acc = 0.f;
                if (s < t) acc = dot8hh(buf_u4[s * 8 + L], hloc_u4[L]);
                acc += __shfl_xor_sync(0xffffffffu, acc, 1);
                acc += __shfl_xor_sync(0xffffffffu, acc, 2);
                acc += __shfl_xor_sync(0xffffffffu, acc, 4);
                if (L == 0 && s < t) scstage[s] = acc;
            }
        }
        if (tid < 256) {
            int grow = (tid >> 6) * 256 + JS * r + (tid & 63);
            xps[tid] = __ldg(&g_xproj[((size_t)t * BB + b) * G4 + grow]);
        }
        __syncthreads();

        // ---- pushes: fp16 h broadcast + fp32 score partials ----
        if (t > 0) {
            if (tid < 32) {               // h halves -> h_full on all ranks
                int dest = tid >> 3, q = tid & 7;
                st_cluster4(smem_u32(&hfull_h[JS * r + q * 8]), dest,
                            *(const float4*)&hloc_h[q * 8]);
            } else if (tid < 160) {       // score partials -> all ranks
                int i = tid - 32, chunk = i >> 2, peer = i & 3;
                if (chunk * 4 < t)
                    st_cluster4(smem_u32(&scp[r * 128 + chunk * 4]), peer,
                                *(const float4*)&scstage[chunk * 4]);
            }
        }
        if (tid < CL) bar_arrive_rank(bar0, tid);
        if (warp == 0) bar_wait(bar0, par);                           // B0
        __syncthreads();

        // ======== P2: [softmax warp0] || [local z/yH GEMV]; y1; hu; push ====
        if (t > 0) {
            {   // local GEMV: 512 thr = 64 rows x (2 hs x 4 chunks), fp16 x
                int row = tid & 63, cg = tid >> 6;   // cg: hs=cg>>2, c=cg&3
                int hs = cg >> 2, c = cg & 3;
                float acc = 0.f;
                #pragma unroll
                for (int i = 0; i < 8; i++) {
                    int k8 = c * 8 + i;
                    acc += dot8hh(waU[hs * 2048 + k8 * 64 + row], hfull_u4[k8]);
                }
                gpart[cg * 64 + row] = acc;
            }
            if (warp == 0) {  // softmax (replicated per rank)
                float v[4];
                float m = -1e30f;
                #pragma unroll
                for (int c = 0; c < 4; c++) {
                    int s = lane + 32 * c;
                    float sum = -1e30f;
                    if (s < t)
                        sum = scp[0 * 128 + s] + scp[1 * 128 + s]
                            + scp[2 * 128 + s] + scp[3 * 128 + s];
                    v[c] = sum;
                    m = fmaxf(m, sum);
                }
                #pragma unroll
                for (int o = 16; o > 0; o >>= 1) m = fmaxf(m, __shfl_xor_sync(0xffffffffu, m, o));
                float tot = 0.f;
                #pragma unroll
                for (int c = 0; c < 4; c++) {
                    int s = lane + 32 * c;
                    if (s < t) { v[c] = __expf(v[c] - m); tot += v[c]; }
                }
                #pragma unroll
                for (int o = 16; o > 0; o >>= 1) tot += __shfl_xor_sync(0xffffffffu, tot, o);
                float inv = 1.f / tot;
                #pragma unroll
                for (int c = 0; c < 4; c++) {
                    int s = lane + 32 * c;
                    if (s < t) alpha[s] = v[c] * inv;
                }
            }
            __syncthreads();

            // reduce GEMV partials (128 thr) + y1 over s<t-1 (all 512 thr)
            if (tid < 128) {
                int hs = tid >> 6, row = tid & 63;
                float v = gpart[(hs * 4 + 0) * 64 + row] + gpart[(hs * 4 + 1) * 64 + row]
                        + gpart[(hs * 4 + 2) * 64 + row] + gpart[(hs * 4 + 3) * 64 + row];
                if (hs == 0) zbuf_h[(t - 1) * 64 + row] = __float2half_rn(v);
                else         yH_loc[row] = v;
            }
            {   // y1 partials over old history only
                int g = tid >> 6, row = tid & 63;
                float acc = 0.f;
                for (int s = g; s < t - 1; s += 8)
                    acc += alpha[s] * __half2float(zbuf_h[s * 64 + row]);
                y1part[g * 64 + row] = acc;
            }
            __syncthreads();

            if (tid < 16) {   // hu rows (4 per thread) -> fp16, push u64 x4
                float hv[4];
                float aT = alpha[t - 1];
                #pragma unroll
                for (int rr = 0; rr < 4; rr++) {
                    int row = tid * 4 + rr;
                    float y = y1part[0 * 64 + row] + y1part[1 * 64 + row]
                            + y1part[2 * 64 + row] + y1part[3 * 64 + row]
                            + y1part[4 * 64 + row] + y1part[5 * 64 + row]
                            + y1part[6 * 64 + row] + y1part[7 * 64 + row]
                            + yH_loc[row]
                            + aT * __half2float(zbuf_h[(t - 1) * 64 + row]);
                    hv[rr] = tanh_fast(y + ba_s[row]);
                }
                __half2 p01 = __floats2half2_rn(hv[0], hv[1]);
                __half2 p23 = __floats2half2_rn(hv[2], hv[3]);
                uint2 pkt;
                pkt.x = *reinterpret_cast<uint32_t*>(&p01);
                pkt.y = *reinterpret_cast<uint32_t*>(&p23);
                #pragma unroll
                for (int dest = 0; dest < CL; dest++)
                    st_cluster2(smem_u32(&hufull_h[JS * r + tid * 4]), dest, pkt);
            }
        }
        if (tid < CL) bar_arrive_rank(bar1, tid);
        if (warp == 0) bar_wait(bar1, par);                           // B1
        __syncthreads();

        // ======== P3: gates GEMV (fp16 HFMA2); 112KB resident, 16KB stream ==
        {
            int hs = tid >> 8, row = tid & 255;
            const uint4* x4 = hufull_u4 + hs * 16;
            float acc = 0.f;
            if (hs == 0) {
                const uint4* W = whhS + row;          // k[0:128)
                #pragma unroll
                for (int i = 0; i < 16; i++)
                    acc += dot8hh(W[i * 256], x4[i]);
            } else {
                const uint4* W = whhS + 4096 + row;   // k[128:224) resident
                #pragma unroll
                for (int i = 0; i < 12; i++)
                    acc += dot8hh(W[i * 256], x4[i]);
                #pragma unroll
                for (int i = 12; i < 16; i++)         // k[224:256) streamed
                    acc += dot8hh(__ldcg(WpHi + i * 256), x4[i]);
            }
            gpart[tid] = acc;
        }
        __syncthreads();

        // ======== fused gates-sum + cell update on my j-slice ===============
        if (tid < JS) {
            int j = JS * r + tid;
            float gv[4];
            #pragma unroll
            for (int g = 0; g < 4; g++) {
                int row = g * 64 + tid;
                gv[g] = gpart[row] + gpart[256 + row] + xps[row];
            }
            float si = 1.f / (1.f + __expf(-gv[0]));
            float sf = 1.f / (1.f + __expf(-gv[1]));
            float so = 1.f / (1.f + __expf(-gv[3]));
            float cn = sf * c_loc[tid] + si * tanh_fast(gv[2]);
            float hn = so * tanh_fast(cn);
            c_loc[tid] = cn;
            __half hn_h = __float2half_rn(hn);
            hloc_h[tid] = hn_h;
            buf_h[t * 64 + tid] = hn_h;

            out[((size_t)t * BB + b) * HH + j] = hn;
            if (t == myLen - 1) {
                out[(size_t)TT * BB * HH + (size_t)b * HH + j] = hn;
                out[(size_t)TT * BB * HH + (size_t)BB * HH + (size_t)b * HH + j] = cn;
            }
        }
        __syncthreads();
    }
}

// ---------------------------------------------------------------------------
extern "C" void kernel_launch(void* const* d_in, const int* in_sizes, int n_in,
                              void* d_out, int out_size)
{
    const float* embs = (const float*)d_in[0];
    const int*   lens = (const int*)  d_in[1];
    const float* W_ih = (const float*)d_in[2];
    const float* W_hh = (const float*)d_in[3];
    const float* b_ih = (const float*)d_in[4];
    const float* b_hh = (const float*)d_in[5];
    const float* W_a  = (const float*)d_in[6];
    const float* b_a  = (const float*)d_in[7];
    float* out = (float*)d_out;

    const int smem_bytes = SMEM_FLOATS * (int)sizeof(float);   // 223,136 B
    cudaFuncSetAttribute(recur_kernel, cudaFuncAttributeMaxDynamicSharedMemorySize, smem_bytes);

    whh16_kernel<<<1024, 256>>>(W_hh);
    xproj_kernel<<<dim3((TT * BB) / 64, G4 / 64), 256>>>(embs, W_ih, b_ih, b_hh);
    recur_kernel<<<BB * CL, NTH, smem_bytes>>>(lens, W_a, b_a, out);
}